// round 12
// baseline (speedup 1.0000x reference)
#include <cuda_runtime.h>
#include <cuda_fp16.h>
#include <cstdint>
#include <cstddef>

// ---------------- problem constants ----------------
#define S_LEN  2048
#define HID    2048
#define NHEAD  16
#define NKVH   4
#define HDIM   128
#define BATCH  2
#define ROWS   (BATCH * S_LEN)      // 4096
#define SCALE  0.08838834764831845f // 1/sqrt(128)

// ---------------- scratch (static device memory; no allocations) ----------------
__device__ float2 g_rope_tab[(size_t)S_LEN * 64];

// fp16 operands
__device__ unsigned short g_xh[(size_t)ROWS * HID];
__device__ unsigned short g_oh[(size_t)ROWS * HID];
__device__ unsigned short g_wqh[(size_t)2048 * HID];   // pre-scaled by SCALE
__device__ unsigned short g_wkh[(size_t)512 * HID];
__device__ unsigned short g_wvh[(size_t)512 * HID];
__device__ unsigned short g_woh[(size_t)2048 * HID];
__device__ unsigned short g_qh[(size_t)ROWS * NHEAD * HDIM];   // roped, scaled
__device__ unsigned short g_kh[(size_t)ROWS * NKVH * HDIM];    // roped
__device__ unsigned short g_vth[(size_t)BATCH * NKVH * HDIM * S_LEN];

// ================= mma.sync / ldmatrix / cp.async helpers =================
__device__ __forceinline__ void mma_f16(float* c, const uint32_t* a, const uint32_t* b)
{
    asm volatile(
        "mma.sync.aligned.m16n8k16.row.col.f32.f16.f16.f32 "
        "{%0,%1,%2,%3}, {%4,%5,%6,%7}, {%8,%9}, {%0,%1,%2,%3};"
        : "+f"(c[0]), "+f"(c[1]), "+f"(c[2]), "+f"(c[3])
        : "r"(a[0]), "r"(a[1]), "r"(a[2]), "r"(a[3]), "r"(b[0]), "r"(b[1]));
}
__device__ __forceinline__ void ldsm_x4(uint32_t* r, uint32_t addr)
{
    asm volatile("ldmatrix.sync.aligned.m8n8.x4.shared.b16 {%0,%1,%2,%3}, [%4];"
        : "=r"(r[0]), "=r"(r[1]), "=r"(r[2]), "=r"(r[3]) : "r"(addr));
}
__device__ __forceinline__ uint32_t smem_u32(const void* p) {
    uint32_t a;
    asm("{ .reg .u64 t; cvta.to.shared.u64 t, %1; cvt.u32.u64 %0, t; }" : "=r"(a) : "l"(p));
    return a;
}
__device__ __forceinline__ void cp_async16(uint32_t dst, const void* src) {
    asm volatile("cp.async.cg.shared.global [%0], [%1], 16;" :: "r"(dst), "l"(src));
}
#define CP_COMMIT() asm volatile("cp.async.commit_group;" ::: "memory")
#define CP_WAIT1()  asm volatile("cp.async.wait_group 1;" ::: "memory")
#define CP_WAIT0()  asm volatile("cp.async.wait_group 0;" ::: "memory")

__device__ __forceinline__ unsigned short f2h(float v) {
    __half h = __float2half_rn(v);
    return *(unsigned short*)&h;
}
__device__ __forceinline__ uint32_t pack2h(float a, float b) {
    __half2 h = __floats2half2_rn(a, b);
    return *(uint32_t*)&h;
}

// ================= conversion kernels =================
__global__ void convert_h(const float* __restrict__ src,
                          unsigned short* __restrict__ dst, int total)
{
    int i = blockIdx.x * blockDim.x + threadIdx.x;
    if (i >= total) return;
    dst[i] = f2h(src[i]);
}

// all 4 weight transposes in one launch. z: 0=wq(scaled) 1=wk 2=wv 3=wo
__global__ void transpose_all(const float* __restrict__ wq, const float* __restrict__ wk,
                              const float* __restrict__ wv, const float* __restrict__ wo,
                              unsigned short* __restrict__ wqh, unsigned short* __restrict__ wkh,
                              unsigned short* __restrict__ wvh, unsigned short* __restrict__ woh)
{
    const int z = blockIdx.z;
    const float* src; unsigned short* dst; int N; float scale = 1.0f;
    if (z == 0)      { src = wq; dst = wqh; N = 2048; scale = SCALE; }
    else if (z == 1) { src = wk; dst = wkh; N = 512; }
    else if (z == 2) { src = wv; dst = wvh; N = 512; }
    else             { src = wo; dst = woh; N = 2048; }
    if (blockIdx.x * 32 >= N) return;

    __shared__ float t[32][33];
    const int n0 = blockIdx.x * 32, k0 = blockIdx.y * 32;
    const int tx = threadIdx.x, ty = threadIdx.y;  // (32, 8)
    #pragma unroll
    for (int i = 0; i < 4; i++)
        t[ty + i * 8][tx] = src[(size_t)(k0 + ty + i * 8) * N + n0 + tx];
    __syncthreads();
    #pragma unroll
    for (int i = 0; i < 4; i++) {
        int n = ty + i * 8;
        dst[(size_t)(n0 + n) * HID + k0 + tx] = f2h(t[tx][n] * scale);
    }
}

// ================= rope table =================
__global__ void fill_rope_table()
{
    int idx = blockIdx.x * blockDim.x + threadIdx.x;
    if (idx >= S_LEN * 64) return;
    int d = idx & 63, pos = idx >> 6;
    double inv = pow(10000.0, -((double)(2 * d)) / 128.0);
    double cd, sd;
    sincos((double)pos * inv, &sd, &cd);
    g_rope_tab[idx] = make_float2((float)cd, (float)sd);
}

// ================= fp16 GEMM: 128 thr, warp tile 64x64, 3-stage cp.async =================
// C tile 128x128. modes: 0 = fp32 C; 1 = rope + fp16 row-major; 2 = fp16 transposed (vth)
#define KTILE    64
#define NT_STEPS (HID / KTILE)      // 32
#define APITCH   72                 // u16 smem pitch (144B)
#define TILE_U16 (128 * APITCH)     // 9216
#define BUF_U16  (2 * TILE_U16)     // A + B per stage
#define NSTAGE   3
#define GEMM_SMEM (NSTAGE * BUF_U16 * 2) // 110592 B
#define PITCHF   132                // fp32 staging pitch (epilogue)

__device__ void gemm_mma_body(const unsigned short* __restrict__ Ah,
                              const unsigned short* __restrict__ Bh,
                              int row0, int col0,
                              int mode,
                              float* __restrict__ C, int ldc,            // mode 0
                              unsigned short* __restrict__ O16, int ldo, // mode 1
                              unsigned short* __restrict__ VT, int bg)   // mode 2
{
    extern __shared__ unsigned short sm[];
    const uint32_t sbase = smem_u32(sm);
    const int tid  = threadIdx.x;          // 0..127
    const int wid  = tid >> 5;             // 0..3
    const int lane = tid & 31;
    const int wm   = wid & 1;              // row half (64 rows)
    const int wn   = wid >> 1;             // col half (64 cols)
    const int g    = lane >> 2;
    const int tq   = lane & 3;

    const int lr   = lane & 7;
    const int oaR  = (lane & 8)  ? 8 : 0;
    const int oaC  = (lane & 16) ? 8 : 0;
    const int obR  = (lane & 16) ? 8 : 0;
    const int obC  = (lane & 8)  ? 8 : 0;
    const int rowA0 = wm * 64 + lr + oaR;
    const int rowB0 = wn * 64 + lr + obR;

    // loader: thread tid owns full row tid of both tiles (64 u16 = 8 cp16)
    const unsigned short* pA = Ah + (size_t)(row0 + tid) * HID;
    const unsigned short* pB = Bh + (size_t)(col0 + tid) * HID;
    const uint32_t dsoff = 2u * (uint32_t)(tid * APITCH);

    float acc[4][8][4];
    #pragma unroll
    for (int mi = 0; mi < 4; mi++)
        #pragma unroll
        for (int ni = 0; ni < 8; ni++)
            #pragma unroll
            for (int e = 0; e < 4; e++) acc[mi][ni][e] = 0.0f;

    auto issue = [&](int t, int buf) {
        const int k0 = t * KTILE;
        const uint32_t a0 = sbase + 2u * (uint32_t)(buf * BUF_U16) + dsoff;
        const uint32_t b0 = a0 + 2u * TILE_U16;
        #pragma unroll
        for (int j = 0; j < 8; j++) cp_async16(a0 + j * 16, pA + k0 + j * 8);
        #pragma unroll
        for (int j = 0; j < 8; j++) cp_async16(b0 + j * 16, pB + k0 + j * 8);
    };

    issue(0, 0); CP_COMMIT();
    issue(1, 1); CP_COMMIT();

    int cur = 0;
    for (int t = 0; t < NT_STEPS; t++) {
        if (t + 1 < NT_STEPS) CP_WAIT1(); else CP_WAIT0();
        __syncthreads();    // stage t visible; all warps done with stage t-1
        if (t + 2 < NT_STEPS) {
            int nb = cur + 2; if (nb >= NSTAGE) nb -= NSTAGE;
            issue(t + 2, nb);
            CP_COMMIT();
        }

        const uint32_t aH = sbase + 2u * (uint32_t)(cur * BUF_U16);
        const uint32_t bH = aH + 2u * TILE_U16;

        #pragma unroll
        for (int ks = 0; ks < KTILE; ks += 16) {
            uint32_t af[4][4], bfr[4][4];
            #pragma unroll
            for (int mi = 0; mi < 4; mi++)
                ldsm_x4(af[mi], aH + 2u * (uint32_t)((rowA0 + mi * 16) * APITCH + ks + oaC));
            #pragma unroll
            for (int jj = 0; jj < 4; jj++)
                ldsm_x4(bfr[jj], bH + 2u * (uint32_t)((rowB0 + jj * 16) * APITCH + ks + obC));
            #pragma unroll
            for (int mi = 0; mi < 4; mi++)
                #pragma unroll
                for (int jj = 0; jj < 4; jj++) {
                    mma_f16(acc[mi][2*jj],   af[mi], &bfr[jj][0]);
                    mma_f16(acc[mi][2*jj+1], af[mi], &bfr[jj][2]);
                }
        }
        if (++cur >= NSTAGE) cur = 0;
    }

    if (mode == 0) {
        #pragma unroll
        for (int mi = 0; mi < 4; mi++) {
            const int mrow = row0 + wm * 64 + mi * 16 + g;
            #pragma unroll
            for (int ni = 0; ni < 8; ni++) {
                const int ncol = col0 + wn * 64 + ni * 8 + tq * 2;
                *(float2*)(C + (size_t)mrow * ldc + ncol)       = make_float2(acc[mi][ni][0], acc[mi][ni][1]);
                *(float2*)(C + (size_t)(mrow + 8) * ldc + ncol) = make_float2(acc[mi][ni][2], acc[mi][ni][3]);
            }
        }
        return;
    }

    __syncthreads();   // all warps done reading smem before staging overwrite

    // ---- stage fp32 accumulators into smem ----
    float* stf = (float*)sm;
    #pragma unroll
    for (int mi = 0; mi < 4; mi++) {
        const int rl = wm * 64 + mi * 16 + g;
        #pragma unroll
        for (int ni = 0; ni < 8; ni++) {
            const int cl = wn * 64 + ni * 8 + tq * 2;
            stf[rl * PITCHF + cl]           = acc[mi][ni][0];
            stf[rl * PITCHF + cl + 1]       = acc[mi][ni][1];
            stf[(rl + 8) * PITCHF + cl]     = acc[mi][ni][2];
            stf[(rl + 8) * PITCHF + cl + 1] = acc[mi][ni][3];
        }
    }
    __syncthreads();

    if (mode == 1) {
        // rope (pairs d, d+64) -> fp16 row-major; thread tid owns row tid
        const int rr = tid;
        const int pos = (row0 + rr) & (S_LEN - 1);
        unsigned short b1[64], b2[64];
        #pragma unroll
        for (int d = 0; d < 64; d++) {
            float x1 = stf[rr * PITCHF + d];
            float x2 = stf[rr * PITCHF + d + 64];
            float2 cs = g_rope_tab[pos * 64 + d];
            b1[d] = f2h(x1 * cs.x - x2 * cs.y);
            b2[d] = f2h(x2 * cs.x + x1 * cs.y);
        }
        unsigned short* o1 = O16 + (size_t)(row0 + rr) * ldo + col0;
        #pragma unroll
        for (int j = 0; j < 8; j++) *(uint4*)(o1 + j * 8)      = ((uint4*)b1)[j];
        #pragma unroll
        for (int j = 0; j < 8; j++) *(uint4*)(o1 + 64 + j * 8) = ((uint4*)b2)[j];
    } else {
        // mode 2: V -> transposed fp16 vth[(bg*128 + d) * S_LEN + key]; thread owns dim d=tid
        const int d = tid;
        unsigned short vb[128];
        #pragma unroll
        for (int i = 0; i < 128; i++)
            vb[i] = f2h(stf[i * PITCHF + d]);
        unsigned short* o = VT + ((size_t)bg * 128 + d) * S_LEN + (row0 & (S_LEN - 1));
        #pragma unroll
        for (int j = 0; j < 16; j++) *(uint4*)(o + j * 8) = ((uint4*)vb)[j];
    }
}

// fused QKV: grid.x 0..15 -> q heads, 16..19 -> k heads, 20..23 -> v heads
__global__ void __launch_bounds__(128, 2)
qkv_tc(const unsigned short* xh,
       const unsigned short* wqh, const unsigned short* wkh, const unsigned short* wvh,
       unsigned short* qh, unsigned short* kh, unsigned short* vth)
{
    const int bx = blockIdx.x;
    const int row0 = blockIdx.y * 128;
    if (bx < 16) {
        gemm_mma_body(xh, wqh, row0, bx * 128, 1, nullptr, 0, qh, 2048, nullptr, 0);
    } else if (bx < 20) {
        gemm_mma_body(xh, wkh, row0, (bx - 16) * 128, 1, nullptr, 0, kh, 512, nullptr, 0);
    } else {
        const int col0 = (bx - 20) * 128;
        const int bg = (row0 >> 11) * 4 + (col0 >> 7);
        gemm_mma_body(xh, wvh, row0, col0, 2, nullptr, 0, nullptr, 0, vth, bg);
    }
}

__global__ void __launch_bounds__(128, 2)
out_tc(const unsigned short* oh, const unsigned short* woh, float* C)
{
    gemm_mma_body(oh, woh, blockIdx.y * 128, blockIdx.x * 128, 0, C, 2048,
                  nullptr, 0, nullptr, 0);
}

// ================= flash attention: mma.sync fp16, double-buffered K/V =================
// grid (S/64, NH, B); block 128 (4 warps); warp owns 16 q rows; kv tile 64 keys.
#define AKP 136
#define AVP 72
#define STG_U16 (64 * AKP + 128 * AVP)   // 17920 u16 per stage
#define SVOFF   (64 * AKP)
#define ATT_SMEM (2 * STG_U16 * 2)       // 71680 B

__global__ void __launch_bounds__(128)
attn_mma(const unsigned short* __restrict__ Qh,
         const unsigned short* __restrict__ Kh,
         const unsigned short* __restrict__ Vth,
         unsigned short* __restrict__ Oh)
{
    const int qt = blockIdx.x;
    const int h  = blockIdx.y;
    const int b  = blockIdx.z;
    const int g4 = h >> 2;
    const int bg = b * 4 + g4;

    extern __shared__ unsigned short smu[];
    const uint32_t sbase = smem_u32(smu);

    const int tid  = threadIdx.x;
    const int wid  = tid >> 5;
    const int lane = tid & 31;
    const int gr   = lane >> 2;
    const int tq   = lane & 3;

    const int lr    = lane & 7;
    const int off8a = (lane & 8)  ? 8 : 0;
    const int off8b = (lane & 16) ? 8 : 0;

    // ---- Q fragments: direct fp16 loads (pre-scaled, pre-roped) ----
    const int q0 = qt * 64 + wid * 16;
    const unsigned short* pq0 = Qh + (size_t)(b * S_LEN + q0 + gr) * 2048 + h * 128;
    const unsigned short* pq1 = Qh + (size_t)(b * S_LEN + q0 + gr + 8) * 2048 + h * 128;
    uint32_t qh[8][4];
    #pragma unroll
    for (int ks = 0; ks < 8; ks++) {
        qh[ks][0] = *(const uint32_t*)(pq0 + 16 * ks + 2 * tq);
        qh[ks][1] = *(const uint32_t*)(pq1 + 16 * ks + 2 * tq);
        qh[ks][2] = *(const uint32_t*)(pq0 + 16 * ks + 2 * tq + 8);
        qh[ks][3] = *(const uint32_t*)(pq1 + 16 * ks + 2 * tq + 8);
    }

    float o[16][4];
    #pragma unroll
    for (int j = 0; j < 16; j++)
        #pragma unroll
        for (int e = 0; e < 4; e++) o[j][e] = 0.0f;
    float m0 = -1e30f, m1 = -1e30f, l0 = 0.0f, l1 = 0.0f;

    const unsigned short* kh_base  = Kh  + ((size_t)(b * S_LEN) * 4 + g4) * 128;
    const unsigned short* vth_base = Vth + (size_t)bg * 128 * S_LEN;

    auto load_tile = [&](int kt, int buf) {
        const uint32_t sb = sbase + 2u * (uint32_t)(buf * STG_U16);
        const unsigned short* src_k = kh_base + (size_t)(kt * 64) * 512;
        #pragma unroll
        for (int i = 0; i < 8; i++) {
            int idx = tid + i * 128;
            int row = idx >> 4, seg = (idx & 15) * 8;
            cp_async16(sb + 2u * (uint32_t)(row * AKP + seg), src_k + (size_t)row * 512 + seg);
        }
        const unsigned short* src_v = vth_base + kt * 64;
        #pragma unroll
        for (int i = 0; i < 8; i++) {
            int idx = tid + i * 128;
            int row = idx >> 3, seg = (idx & 7) * 8;
            cp_async16(sb + 2u * (uint32_t)(SVOFF + row * AVP + seg), src_v + (size_t)row * S_LEN + seg);
        }
    };

    load_tile(0, 0); CP_COMMIT();

    for (int kt = 0; kt <= qt; kt++) {
        const int buf = kt & 1;
        if (kt < qt) {
            load_tile(kt + 1, buf ^ 1);
            CP_COMMIT();
            CP_WAIT1();
        } else {
            CP_WAIT0();
        }
        __syncthreads();

        const uint32_t stg = sbase + 2u * (uint32_t)(buf * STG_U16);

        // ---- scores ----
        float s[8][4];
        #pragma unroll
        for (int j = 0; j < 8; j++)
            #pragma unroll
            for (int e = 0; e < 4; e++) s[j][e] = 0.0f;

        #pragma unroll
        for (int jj = 0; jj < 4; jj++) {
            #pragma unroll
            for (int ks = 0; ks < 8; ks++) {
                uint32_t khf[4];
                ldsm_x4(khf, stg + 2u * (uint32_t)((16 * jj + off8b + lr) * AKP + 16 * ks + off8a));
                mma_f16(s[2*jj],   qh[ks], khf + 0);
                mma_f16(s[2*jj+1], qh[ks], khf + 2);
            }
        }

        if (kt == qt) {
            const int rl0 = wid * 16 + gr;
            const int rl1 = rl0 + 8;
            #pragma unroll
            for (int j = 0; j < 8; j++) {
                int c0 = 8 * j + 2 * tq, c1 = c0 + 1;
                if (c0 > rl0) s[j][0] = -1e30f;
                if (c1 > rl0) s[j][1] = -1e30f;
                if (c0 > rl1) s[j][2] = -1e30f;
                if (c1 > rl1) s[j][3] = -1e30f;
            }
        }

        // ---- online softmax ----
        float mx0 = -1e30f, mx1 = -1e30f;
        #pragma unroll
        for (int j = 0; j < 8; j++) {
            mx0 = fmaxf(mx0, fmaxf(s[j][0], s[j][1]));
            mx1 = fmaxf(mx1, fmaxf(s[j][2], s[j][3]));
        }
        mx0 = fmaxf(mx0, __shfl_xor_sync(0xffffffffu, mx0, 1));
        mx0 = fmaxf(mx0, __shfl_xor_sync(0xffffffffu, mx0, 2));
        mx1 = fmaxf(mx1, __shfl_xor_sync(0xffffffffu, mx1, 1));
        mx1 = fmaxf(mx1, __shfl_xor_sync(0xffffffffu, mx1, 2));

        float mn0 = fmaxf(m0, mx0), mn1 = fmaxf(m1, mx1);
        float c0 = __expf(m0 - mn0), c1 = __expf(m1 - mn1);

        uint32_t ph[8][2];
        float sum0 = 0.0f, sum1 = 0.0f;
        #pragma unroll
        for (int j = 0; j < 8; j++) {
            float p0 = __expf(s[j][0] - mn0);
            float p1 = __expf(s[j][1] - mn0);
            float p2 = __expf(s[j][2] - mn1);
            float p3 = __expf(s[j][3] - mn1);
            sum0 += p0 + p1;
            sum1 += p2 + p3;
            ph[j][0] = pack2h(p0, p1);
            ph[j][1] = pack2h(p2, p3);
        }
        sum0 += __shfl_xor_sync(0xffffffffu, sum0, 1);
        sum0 += __shfl_xor_sync(0xffffffffu, sum0, 2);
        sum1 += __shfl_xor_sync(0xffffffffu, sum1, 1);
        sum1 += __shfl_xor_sync(0xffffffffu, sum1, 2);
        l0 = l0 * c0 + sum0;
        l1 = l1 * c1 + sum1;
        m0 = mn0; m1 = mn1;
        #pragma unroll
        for (int j = 0; j < 16; j++) {
            o[j][0] *= c0; o[j][1] *= c0;
            o[j][2] *= c1; o[j][3] *= c1;
        }

        // ---- PV ----
        #pragma unroll
        for (int ks = 0; ks < 4; ks++) {
            uint32_t ah4[4] = { ph[2*ks][0], ph[2*ks][1], ph[2*ks+1][0], ph[2*ks+1][1] };
            #pragma unroll
            for (int jj = 0; jj < 8; jj++) {
                uint32_t vhf[4];
                ldsm_x4(vhf, stg + 2u * (uint32_t)(SVOFF + (16 * jj + off8b + lr) * AVP + 16 * ks + off8a));
                mma_f16(o[2*jj],   ah4, vhf + 0);
                mma_f16(o[2*jj+1], ah4, vhf + 2);
            }
        }
        __syncthreads();
    }

    // ---- epilogue: normalize, store fp16 ----
    const float inv0 = 1.0f / l0, inv1 = 1.0f / l1;
    const size_t rowA = (size_t)(b * S_LEN + q0 + gr) * 2048 + h * 128;
    const size_t rowB = (size_t)(b * S_LEN + q0 + gr + 8) * 2048 + h * 128;
    #pragma unroll
    for (int j = 0; j < 16; j++) {
        const int col = 8 * j + 2 * tq;
        *(uint32_t*)(Oh + rowA + col) = pack2h(o[j][0] * inv0, o[j][1] * inv0);
        *(uint32_t*)(Oh + rowB + col) = pack2h(o[j][2] * inv1, o[j][3] * inv1);
    }
}

// ================= launch =================
extern "C" void kernel_launch(void* const* d_in, const int* in_sizes, int n_in,
                              void* d_out, int out_size)
{
    const float* x  = (const float*)d_in[0];
    const float* wq = (const float*)d_in[1];
    const float* wk = (const float*)d_in[2];
    const float* wv = (const float*)d_in[3];
    const float* wo = (const float*)d_in[4];
    float* out = (float*)d_out;

    unsigned short *xh, *oh, *wqh, *wkh, *wvh, *woh, *qh, *kh, *vth;
    cudaGetSymbolAddress((void**)&xh, g_xh);
    cudaGetSymbolAddress((void**)&oh, g_oh);
    cudaGetSymbolAddress((void**)&wqh, g_wqh);
    cudaGetSymbolAddress((void**)&wkh, g_wkh);
    cudaGetSymbolAddress((void**)&wvh, g_wvh);
    cudaGetSymbolAddress((void**)&woh, g_woh);
    cudaGetSymbolAddress((void**)&qh, g_qh);
    cudaGetSymbolAddress((void**)&kh, g_kh);
    cudaGetSymbolAddress((void**)&vth, g_vth);

    cudaFuncSetAttribute(qkv_tc, cudaFuncAttributeMaxDynamicSharedMemorySize, GEMM_SMEM);
    cudaFuncSetAttribute(out_tc, cudaFuncAttributeMaxDynamicSharedMemorySize, GEMM_SMEM);
    cudaFuncSetAttribute(attn_mma, cudaFuncAttributeMaxDynamicSharedMemorySize, ATT_SMEM);

    // 0. rope table + operand conversion
    fill_rope_table<<<(S_LEN * 64 + 255) / 256, 256>>>();
    convert_h<<<(ROWS * HID + 255) / 256, 256>>>(x, xh, ROWS * HID);
    transpose_all<<<dim3(64, 64, 4), dim3(32, 8)>>>(wq, wk, wv, wo, wqh, wkh, wvh, woh);

    // 1. fused QKV projections + rope + quantize + V-transpose (fat warp tiles)
    qkv_tc<<<dim3(24, ROWS / 128), 128, GEMM_SMEM>>>(xh, wqh, wkh, wvh, qh, kh, vth);

    // 2. flash attention (fp16 mma, double-buffered); writes oh directly
    attn_mma<<<dim3(S_LEN / 64, NHEAD, BATCH), 128, ATT_SMEM>>>(qh, kh, vth, oh);

    // 3. output projection
    out_tc<<<dim3(HID / 128, ROWS / 128), 128, GEMM_SMEM>>>(oh, woh, out);
}

// round 14
// speedup vs baseline: 1.0996x; 1.0996x over previous
#include <cuda_runtime.h>
#include <cuda_fp16.h>
#include <cstdint>
#include <cstddef>

// ---------------- problem constants ----------------
#define S_LEN  2048
#define HID    2048
#define NHEAD  16
#define NKVH   4
#define HDIM   128
#define BATCH  2
#define ROWS   (BATCH * S_LEN)      // 4096
#define SCALE  0.08838834764831845f // 1/sqrt(128)

// ---------------- scratch (static device memory; no allocations) ----------------
__device__ float2 g_rope_tab[(size_t)S_LEN * 64];

// fp16 operands
__device__ unsigned short g_xh[(size_t)ROWS * HID];
__device__ unsigned short g_oh[(size_t)ROWS * HID];
__device__ unsigned short g_wqh[(size_t)2048 * HID];   // pre-scaled by SCALE
__device__ unsigned short g_wkh[(size_t)512 * HID];
__device__ unsigned short g_wvh[(size_t)512 * HID];
__device__ unsigned short g_woh[(size_t)2048 * HID];
__device__ unsigned short g_qh[(size_t)ROWS * NHEAD * HDIM];   // roped, scaled
__device__ unsigned short g_kh[(size_t)ROWS * NKVH * HDIM];    // roped
__device__ unsigned short g_vth[(size_t)BATCH * NKVH * HDIM * S_LEN];

// ================= mma.sync / ldmatrix / cp.async helpers =================
__device__ __forceinline__ void mma_f16(float* c, const uint32_t* a, const uint32_t* b)
{
    asm volatile(
        "mma.sync.aligned.m16n8k16.row.col.f32.f16.f16.f32 "
        "{%0,%1,%2,%3}, {%4,%5,%6,%7}, {%8,%9}, {%0,%1,%2,%3};"
        : "+f"(c[0]), "+f"(c[1]), "+f"(c[2]), "+f"(c[3])
        : "r"(a[0]), "r"(a[1]), "r"(a[2]), "r"(a[3]), "r"(b[0]), "r"(b[1]));
}
__device__ __forceinline__ void ldsm_x4(uint32_t* r, uint32_t addr)
{
    asm volatile("ldmatrix.sync.aligned.m8n8.x4.shared.b16 {%0,%1,%2,%3}, [%4];"
        : "=r"(r[0]), "=r"(r[1]), "=r"(r[2]), "=r"(r[3]) : "r"(addr));
}
__device__ __forceinline__ uint32_t smem_u32(const void* p) {
    uint32_t a;
    asm("{ .reg .u64 t; cvta.to.shared.u64 t, %1; cvt.u32.u64 %0, t; }" : "=r"(a) : "l"(p));
    return a;
}
__device__ __forceinline__ void cp_async16(uint32_t dst, const void* src) {
    asm volatile("cp.async.cg.shared.global [%0], [%1], 16;" :: "r"(dst), "l"(src));
}
#define CP_COMMIT() asm volatile("cp.async.commit_group;" ::: "memory")
#define CP_WAIT1()  asm volatile("cp.async.wait_group 1;" ::: "memory")
#define CP_WAIT0()  asm volatile("cp.async.wait_group 0;" ::: "memory")

__device__ __forceinline__ unsigned short f2h(float v) {
    __half h = __float2half_rn(v);
    return *(unsigned short*)&h;
}
__device__ __forceinline__ uint32_t pack2h(float a, float b) {
    __half2 h = __floats2half2_rn(a, b);
    return *(uint32_t*)&h;
}

// ================= conversion kernels =================
__global__ void convert_h(const float* __restrict__ src,
                          unsigned short* __restrict__ dst, int total)
{
    int i = blockIdx.x * blockDim.x + threadIdx.x;
    if (i >= total) return;
    dst[i] = f2h(src[i]);
}

// all 4 weight transposes in one launch. z: 0=wq(scaled) 1=wk 2=wv 3=wo
__global__ void transpose_all(const float* __restrict__ wq, const float* __restrict__ wk,
                              const float* __restrict__ wv, const float* __restrict__ wo,
                              unsigned short* __restrict__ wqh, unsigned short* __restrict__ wkh,
                              unsigned short* __restrict__ wvh, unsigned short* __restrict__ woh)
{
    const int z = blockIdx.z;
    const float* src; unsigned short* dst; int N; float scale = 1.0f;
    if (z == 0)      { src = wq; dst = wqh; N = 2048; scale = SCALE; }
    else if (z == 1) { src = wk; dst = wkh; N = 512; }
    else if (z == 2) { src = wv; dst = wvh; N = 512; }
    else             { src = wo; dst = woh; N = 2048; }
    if (blockIdx.x * 32 >= N) return;

    __shared__ float t[32][33];
    const int n0 = blockIdx.x * 32, k0 = blockIdx.y * 32;
    const int tx = threadIdx.x, ty = threadIdx.y;  // (32, 8)
    #pragma unroll
    for (int i = 0; i < 4; i++)
        t[ty + i * 8][tx] = src[(size_t)(k0 + ty + i * 8) * N + n0 + tx];
    __syncthreads();
    #pragma unroll
    for (int i = 0; i < 4; i++) {
        int n = ty + i * 8;
        dst[(size_t)(n0 + n) * HID + k0 + tx] = f2h(t[tx][n] * scale);
    }
}

// ================= rope table =================
__global__ void fill_rope_table()
{
    int idx = blockIdx.x * blockDim.x + threadIdx.x;
    if (idx >= S_LEN * 64) return;
    int d = idx & 63, pos = idx >> 6;
    double inv = pow(10000.0, -((double)(2 * d)) / 128.0);
    double cd, sd;
    sincos((double)pos * inv, &sd, &cd);
    g_rope_tab[idx] = make_float2((float)cd, (float)sd);
}

// ================= fp16 GEMM: 256 thr, CTA 64x128, warp tile 32x32, 3 CTA/SM =================
// modes: 0 = fp32 C; 1 = rope + fp16 row-major; 2 = fp16 transposed (vth)
#define KTILE    64
#define NT_STEPS (HID / KTILE)      // 32
#define APITCH   72                 // u16 smem pitch (144B)
#define A_U16    (64 * APITCH)      // 4608
#define B_U16    (128 * APITCH)     // 9216
#define BUF_U16  (A_U16 + B_U16)    // 13824
#define GEMM_SMEM (2 * BUF_U16 * 2) // 55296 B
#define PITCHF   132                // fp32 staging pitch (epilogue)

__device__ void gemm_mma_body(const unsigned short* __restrict__ Ah,
                              const unsigned short* __restrict__ Bh,
                              int row0, int col0,
                              int mode,
                              float* __restrict__ C, int ldc,            // mode 0
                              unsigned short* __restrict__ O16, int ldo, // mode 1
                              unsigned short* __restrict__ VT, int bg)   // mode 2
{
    extern __shared__ unsigned short sm[];
    const uint32_t sbase = smem_u32(sm);
    const int tid  = threadIdx.x;          // 0..255
    const int wid  = tid >> 5;             // 0..7
    const int lane = tid & 31;
    const int wm   = wid & 1;              // 2 row groups of 32
    const int wn   = wid >> 1;             // 4 col groups of 32
    const int g    = lane >> 2;
    const int tq   = lane & 3;

    const int lr   = lane & 7;
    const int oaR  = (lane & 8)  ? 8 : 0;
    const int oaC  = (lane & 16) ? 8 : 0;
    const int obR  = (lane & 16) ? 8 : 0;
    const int obC  = (lane & 8)  ? 8 : 0;
    const int rowA0 = wm * 32 + lr + oaR;
    const int rowB0 = wn * 32 + lr + obR;

    // loaders: A 64 rows (4 thr/row, 16 u16 each); B 128 rows (2 thr/row, 32 u16 each)
    const int ar = tid >> 2, aq = tid & 3;
    const int br = tid >> 1, bhf2 = tid & 1;
    const unsigned short* pA = Ah + (size_t)(row0 + ar) * HID + aq * 16;
    const unsigned short* pB = Bh + (size_t)(col0 + br) * HID + bhf2 * 32;
    const uint32_t daoff = 2u * (uint32_t)(ar * APITCH + aq * 16);
    const uint32_t dboff = 2u * (uint32_t)(A_U16 + br * APITCH + bhf2 * 32);

    float acc[2][4][4];
    #pragma unroll
    for (int mi = 0; mi < 2; mi++)
        #pragma unroll
        for (int ni = 0; ni < 4; ni++)
            #pragma unroll
            for (int e = 0; e < 4; e++) acc[mi][ni][e] = 0.0f;

    auto issue = [&](int t, int buf) {
        const int k0 = t * KTILE;
        const uint32_t base = sbase + 2u * (uint32_t)(buf * BUF_U16);
        cp_async16(base + daoff,      pA + k0);
        cp_async16(base + daoff + 16, pA + k0 + 8);
        cp_async16(base + dboff,      pB + k0);
        cp_async16(base + dboff + 16, pB + k0 + 8);
        cp_async16(base + dboff + 32, pB + k0 + 16);
        cp_async16(base + dboff + 48, pB + k0 + 24);
    };

    issue(0, 0); CP_COMMIT();

    for (int t = 0; t < NT_STEPS; t++) {
        const int cur = t & 1;
        if (t + 1 < NT_STEPS) {
            issue(t + 1, cur ^ 1);   // prefetch into inactive buffer only
            CP_COMMIT();
            CP_WAIT1();              // wait for tile t (one group pending: t+1)
        } else {
            CP_WAIT0();
        }
        __syncthreads();             // tile t visible to all warps

        const uint32_t aH = sbase + 2u * (uint32_t)(cur * BUF_U16);
        const uint32_t bH = aH + 2u * A_U16;

        #pragma unroll
        for (int ks = 0; ks < KTILE; ks += 16) {
            uint32_t af[2][4], bfr[2][4];
            #pragma unroll
            for (int mi = 0; mi < 2; mi++)
                ldsm_x4(af[mi], aH + 2u * (uint32_t)((rowA0 + mi * 16) * APITCH + ks + oaC));
            #pragma unroll
            for (int jj = 0; jj < 2; jj++)
                ldsm_x4(bfr[jj], bH + 2u * (uint32_t)((rowB0 + jj * 16) * APITCH + ks + obC));
            #pragma unroll
            for (int mi = 0; mi < 2; mi++)
                #pragma unroll
                for (int jj = 0; jj < 2; jj++) {
                    mma_f16(acc[mi][2*jj],   af[mi], &bfr[jj][0]);
                    mma_f16(acc[mi][2*jj+1], af[mi], &bfr[jj][2]);
                }
        }
        __syncthreads();             // all warps done with buffer cur before next prefetch
    }

    if (mode == 0) {
        #pragma unroll
        for (int mi = 0; mi < 2; mi++) {
            const int mrow = row0 + wm * 32 + mi * 16 + g;
            #pragma unroll
            for (int ni = 0; ni < 4; ni++) {
                const int ncol = col0 + wn * 32 + ni * 8 + tq * 2;
                *(float2*)(C + (size_t)mrow * ldc + ncol)       = make_float2(acc[mi][ni][0], acc[mi][ni][1]);
                *(float2*)(C + (size_t)(mrow + 8) * ldc + ncol) = make_float2(acc[mi][ni][2], acc[mi][ni][3]);
            }
        }
        return;
    }

    // ---- stage fp32 accumulators into smem (64 rows x 128 cols) ----
    float* stf = (float*)sm;
    #pragma unroll
    for (int mi = 0; mi < 2; mi++) {
        const int rl = wm * 32 + mi * 16 + g;
        #pragma unroll
        for (int ni = 0; ni < 4; ni++) {
            const int cl = wn * 32 + ni * 8 + tq * 2;
            stf[rl * PITCHF + cl]           = acc[mi][ni][0];
            stf[rl * PITCHF + cl + 1]       = acc[mi][ni][1];
            stf[(rl + 8) * PITCHF + cl]     = acc[mi][ni][2];
            stf[(rl + 8) * PITCHF + cl + 1] = acc[mi][ni][3];
        }
    }
    __syncthreads();

    if (mode == 1) {
        // rope (pairs d, d+64 within 128-col head tile); 4 threads per row
        const int rr = tid >> 2;            // 0..63
        const int quarter = tid & 3;        // 16 pairs each
        const int pos = (row0 + rr) & (S_LEN - 1);
        unsigned short b1[16], b2[16];
        #pragma unroll
        for (int i = 0; i < 16; i++) {
            const int d = quarter * 16 + i;
            float x1 = stf[rr * PITCHF + d];
            float x2 = stf[rr * PITCHF + d + 64];
            float2 cs = g_rope_tab[pos * 64 + d];
            b1[i] = f2h(x1 * cs.x - x2 * cs.y);
            b2[i] = f2h(x2 * cs.x + x1 * cs.y);
        }
        unsigned short* o1 = O16 + (size_t)(row0 + rr) * ldo + col0 + quarter * 16;
        *(uint4*)(o1)          = ((uint4*)b1)[0];
        *(uint4*)(o1 + 8)      = ((uint4*)b1)[1];
        *(uint4*)(o1 + 64)     = ((uint4*)b2)[0];
        *(uint4*)(o1 + 64 + 8) = ((uint4*)b2)[1];
    } else {
        // mode 2: V -> transposed fp16 vth[(bg*128 + d) * S_LEN + key]; 64 keys per tile
        const int d    = tid >> 1;          // 0..127
        const int keyh = tid & 1;           // 32 keys each
        unsigned short vb[32];
        #pragma unroll
        for (int i = 0; i < 32; i++)
            vb[i] = f2h(stf[(keyh * 32 + i) * PITCHF + d]);
        unsigned short* o = VT + ((size_t)bg * 128 + d) * S_LEN + (row0 & (S_LEN - 1)) + keyh * 32;
        #pragma unroll
        for (int j = 0; j < 4; j++) *(uint4*)(o + j * 8) = ((uint4*)vb)[j];
    }
}

// fused QKV: grid.x 0..15 -> q heads, 16..19 -> k heads, 20..23 -> v heads; grid.y = 64 row tiles
__global__ void __launch_bounds__(256, 3)
qkv_tc(const unsigned short* xh,
       const unsigned short* wqh, const unsigned short* wkh, const unsigned short* wvh,
       unsigned short* qh, unsigned short* kh, unsigned short* vth)
{
    const int bx = blockIdx.x;
    const int row0 = blockIdx.y * 64;
    if (bx < 16) {
        gemm_mma_body(xh, wqh, row0, bx * 128, 1, nullptr, 0, qh, 2048, nullptr, 0);
    } else if (bx < 20) {
        gemm_mma_body(xh, wkh, row0, (bx - 16) * 128, 1, nullptr, 0, kh, 512, nullptr, 0);
    } else {
        const int col0 = (bx - 20) * 128;
        const int bg = (row0 >> 11) * 4 + (col0 >> 7);
        gemm_mma_body(xh, wvh, row0, col0, 2, nullptr, 0, nullptr, 0, vth, bg);
    }
}

__global__ void __launch_bounds__(256, 3)
out_tc(const unsigned short* oh, const unsigned short* woh, float* C)
{
    gemm_mma_body(oh, woh, blockIdx.y * 64, blockIdx.x * 128, 0, C, 2048,
                  nullptr, 0, nullptr, 0);
}

// ================= flash attention: mma.sync fp16, double-buffered K/V =================
#define AKP 136
#define AVP 72
#define STG_U16 (64 * AKP + 128 * AVP)   // 17920 u16 per stage
#define SVOFF   (64 * AKP)
#define ATT_SMEM (2 * STG_U16 * 2)       // 71680 B

__global__ void __launch_bounds__(128)
attn_mma(const unsigned short* __restrict__ Qh,
         const unsigned short* __restrict__ Kh,
         const unsigned short* __restrict__ Vth,
         unsigned short* __restrict__ Oh)
{
    const int qt = blockIdx.x;
    const int h  = blockIdx.y;
    const int b  = blockIdx.z;
    const int g4 = h >> 2;
    const int bg = b * 4 + g4;

    extern __shared__ unsigned short smu[];
    const uint32_t sbase = smem_u32(smu);

    const int tid  = threadIdx.x;
    const int wid  = tid >> 5;
    const int lane = tid & 31;
    const int gr   = lane >> 2;
    const int tq   = lane & 3;

    const int lr    = lane & 7;
    const int off8a = (lane & 8)  ? 8 : 0;
    const int off8b = (lane & 16) ? 8 : 0;

    const int q0 = qt * 64 + wid * 16;
    const unsigned short* pq0 = Qh + (size_t)(b * S_LEN + q0 + gr) * 2048 + h * 128;
    const unsigned short* pq1 = Qh + (size_t)(b * S_LEN + q0 + gr + 8) * 2048 + h * 128;
    uint32_t qh[8][4];
    #pragma unroll
    for (int ks = 0; ks < 8; ks++) {
        qh[ks][0] = *(const uint32_t*)(pq0 + 16 * ks + 2 * tq);
        qh[ks][1] = *(const uint32_t*)(pq1 + 16 * ks + 2 * tq);
        qh[ks][2] = *(const uint32_t*)(pq0 + 16 * ks + 2 * tq + 8);
        qh[ks][3] = *(const uint32_t*)(pq1 + 16 * ks + 2 * tq + 8);
    }

    float o[16][4];
    #pragma unroll
    for (int j = 0; j < 16; j++)
        #pragma unroll
        for (int e = 0; e < 4; e++) o[j][e] = 0.0f;
    float m0 = -1e30f, m1 = -1e30f, l0 = 0.0f, l1 = 0.0f;

    const unsigned short* kh_base  = Kh  + ((size_t)(b * S_LEN) * 4 + g4) * 128;
    const unsigned short* vth_base = Vth + (size_t)bg * 128 * S_LEN;

    auto load_tile = [&](int kt, int buf) {
        const uint32_t sb = sbase + 2u * (uint32_t)(buf * STG_U16);
        const unsigned short* src_k = kh_base + (size_t)(kt * 64) * 512;
        #pragma unroll
        for (int i = 0; i < 8; i++) {
            int idx = tid + i * 128;
            int row = idx >> 4, seg = (idx & 15) * 8;
            cp_async16(sb + 2u * (uint32_t)(row * AKP + seg), src_k + (size_t)row * 512 + seg);
        }
        const unsigned short* src_v = vth_base + kt * 64;
        #pragma unroll
        for (int i = 0; i < 8; i++) {
            int idx = tid + i * 128;
            int row = idx >> 3, seg = (idx & 7) * 8;
            cp_async16(sb + 2u * (uint32_t)(SVOFF + row * AVP + seg), src_v + (size_t)row * S_LEN + seg);
        }
    };

    load_tile(0, 0); CP_COMMIT();

    for (int kt = 0; kt <= qt; kt++) {
        const int buf = kt & 1;
        if (kt < qt) {
            load_tile(kt + 1, buf ^ 1);
            CP_COMMIT();
            CP_WAIT1();
        } else {
            CP_WAIT0();
        }
        __syncthreads();

        const uint32_t stg = sbase + 2u * (uint32_t)(buf * STG_U16);

        float s[8][4];
        #pragma unroll
        for (int j = 0; j < 8; j++)
            #pragma unroll
            for (int e = 0; e < 4; e++) s[j][e] = 0.0f;

        #pragma unroll
        for (int jj = 0; jj < 4; jj++) {
            #pragma unroll
            for (int ks = 0; ks < 8; ks++) {
                uint32_t khf[4];
                ldsm_x4(khf, stg + 2u * (uint32_t)((16 * jj + off8b + lr) * AKP + 16 * ks + off8a));
                mma_f16(s[2*jj],   qh[ks], khf + 0);
                mma_f16(s[2*jj+1], qh[ks], khf + 2);
            }
        }

        if (kt == qt) {
            const int rl0 = wid * 16 + gr;
            const int rl1 = rl0 + 8;
            #pragma unroll
            for (int j = 0; j < 8; j++) {
                int c0 = 8 * j + 2 * tq, c1 = c0 + 1;
                if (c0 > rl0) s[j][0] = -1e30f;
                if (c1 > rl0) s[j][1] = -1e30f;
                if (c0 > rl1) s[j][2] = -1e30f;
                if (c1 > rl1) s[j][3] = -1e30f;
            }
        }

        float mx0 = -1e30f, mx1 = -1e30f;
        #pragma unroll
        for (int j = 0; j < 8; j++) {
            mx0 = fmaxf(mx0, fmaxf(s[j][0], s[j][1]));
            mx1 = fmaxf(mx1, fmaxf(s[j][2], s[j][3]));
        }
        mx0 = fmaxf(mx0, __shfl_xor_sync(0xffffffffu, mx0, 1));
        mx0 = fmaxf(mx0, __shfl_xor_sync(0xffffffffu, mx0, 2));
        mx1 = fmaxf(mx1, __shfl_xor_sync(0xffffffffu, mx1, 1));
        mx1 = fmaxf(mx1, __shfl_xor_sync(0xffffffffu, mx1, 2));

        float mn0 = fmaxf(m0, mx0), mn1 = fmaxf(m1, mx1);
        float c0 = __expf(m0 - mn0), c1 = __expf(m1 - mn1);

        uint32_t ph[8][2];
        float sum0 = 0.0f, sum1 = 0.0f;
        #pragma unroll
        for (int j = 0; j < 8; j++) {
            float p0 = __expf(s[j][0] - mn0);
            float p1 = __expf(s[j][1] - mn0);
            float p2 = __expf(s[j][2] - mn1);
            float p3 = __expf(s[j][3] - mn1);
            sum0 += p0 + p1;
            sum1 += p2 + p3;
            ph[j][0] = pack2h(p0, p1);
            ph[j][1] = pack2h(p2, p3);
        }
        sum0 += __shfl_xor_sync(0xffffffffu, sum0, 1);
        sum0 += __shfl_xor_sync(0xffffffffu, sum0, 2);
        sum1 += __shfl_xor_sync(0xffffffffu, sum1, 1);
        sum1 += __shfl_xor_sync(0xffffffffu, sum1, 2);
        l0 = l0 * c0 + sum0;
        l1 = l1 * c1 + sum1;
        m0 = mn0; m1 = mn1;
        #pragma unroll
        for (int j = 0; j < 16; j++) {
            o[j][0] *= c0; o[j][1] *= c0;
            o[j][2] *= c1; o[j][3] *= c1;
        }

        #pragma unroll
        for (int ks = 0; ks < 4; ks++) {
            uint32_t ah4[4] = { ph[2*ks][0], ph[2*ks][1], ph[2*ks+1][0], ph[2*ks+1][1] };
            #pragma unroll
            for (int jj = 0; jj < 8; jj++) {
                uint32_t vhf[4];
                ldsm_x4(vhf, stg + 2u * (uint32_t)(SVOFF + (16 * jj + off8b + lr) * AVP + 16 * ks + off8a));
                mma_f16(o[2*jj],   ah4, vhf + 0);
                mma_f16(o[2*jj+1], ah4, vhf + 2);
            }
        }
        __syncthreads();
    }

    const float inv0 = 1.0f / l0, inv1 = 1.0f / l1;
    const size_t rowA = (size_t)(b * S_LEN + q0 + gr) * 2048 + h * 128;
    const size_t rowB = (size_t)(b * S_LEN + q0 + gr + 8) * 2048 + h * 128;
    #pragma unroll
    for (int j = 0; j < 16; j++) {
        const int col = 8 * j + 2 * tq;
        *(uint32_t*)(Oh + rowA + col) = pack2h(o[j][0] * inv0, o[j][1] * inv0);
        *(uint32_t*)(Oh + rowB + col) = pack2h(o[j][2] * inv1, o[j][3] * inv1);
    }
}

// ================= launch =================
extern "C" void kernel_launch(void* const* d_in, const int* in_sizes, int n_in,
                              void* d_out, int out_size)
{
    const float* x  = (const float*)d_in[0];
    const float* wq = (const float*)d_in[1];
    const float* wk = (const float*)d_in[2];
    const float* wv = (const float*)d_in[3];
    const float* wo = (const float*)d_in[4];
    float* out = (float*)d_out;

    unsigned short *xh, *oh, *wqh, *wkh, *wvh, *woh, *qh, *kh, *vth;
    cudaGetSymbolAddress((void**)&xh, g_xh);
    cudaGetSymbolAddress((void**)&oh, g_oh);
    cudaGetSymbolAddress((void**)&wqh, g_wqh);
    cudaGetSymbolAddress((void**)&wkh, g_wkh);
    cudaGetSymbolAddress((void**)&wvh, g_wvh);
    cudaGetSymbolAddress((void**)&woh, g_woh);
    cudaGetSymbolAddress((void**)&qh, g_qh);
    cudaGetSymbolAddress((void**)&kh, g_kh);
    cudaGetSymbolAddress((void**)&vth, g_vth);

    cudaFuncSetAttribute(qkv_tc, cudaFuncAttributeMaxDynamicSharedMemorySize, GEMM_SMEM);
    cudaFuncSetAttribute(out_tc, cudaFuncAttributeMaxDynamicSharedMemorySize, GEMM_SMEM);
    cudaFuncSetAttribute(attn_mma, cudaFuncAttributeMaxDynamicSharedMemorySize, ATT_SMEM);

    // 0. rope table + operand conversion
    fill_rope_table<<<(S_LEN * 64 + 255) / 256, 256>>>();
    convert_h<<<(ROWS * HID + 255) / 256, 256>>>(x, xh, ROWS * HID);
    transpose_all<<<dim3(64, 64, 4), dim3(32, 8)>>>(wq, wk, wv, wo, wqh, wkh, wvh, woh);

    // 1. fused QKV projections + rope + quantize + V-transpose (64-row tiles, 3 CTA/SM)
    qkv_tc<<<dim3(24, ROWS / 64), 256, GEMM_SMEM>>>(xh, wqh, wkh, wvh, qh, kh, vth);

    // 2. flash attention (fp16 mma, double-buffered); writes oh directly
    attn_mma<<<dim3(S_LEN / 64, NHEAD, BATCH), 128, ATT_SMEM>>>(qh, kh, vth, oh);

    // 3. output projection
    out_tc<<<dim3(HID / 128, ROWS / 64), 256, GEMM_SMEM>>>(oh, woh, out);
}

// round 15
// speedup vs baseline: 1.1417x; 1.0382x over previous
#include <cuda_runtime.h>
#include <cuda_fp16.h>
#include <cstdint>
#include <cstddef>

// ---------------- problem constants ----------------
#define S_LEN  2048
#define HID    2048
#define NHEAD  16
#define NKVH   4
#define HDIM   128
#define BATCH  2
#define ROWS   (BATCH * S_LEN)      // 4096
#define SCALE  0.08838834764831845f // 1/sqrt(128)

// ---------------- scratch (static device memory; no allocations) ----------------
__device__ float2 g_rope_tab[(size_t)S_LEN * 64];

// fp16 operands
__device__ unsigned short g_xh[(size_t)ROWS * HID];
__device__ unsigned short g_oh[(size_t)ROWS * HID];
__device__ unsigned short g_wqh[(size_t)2048 * HID];   // pre-scaled by SCALE
__device__ unsigned short g_wkh[(size_t)512 * HID];
__device__ unsigned short g_wvh[(size_t)512 * HID];
__device__ unsigned short g_woh[(size_t)2048 * HID];
__device__ unsigned short g_qh[(size_t)ROWS * NHEAD * HDIM];   // roped, scaled
__device__ unsigned short g_kh[(size_t)ROWS * NKVH * HDIM];    // roped
__device__ unsigned short g_vth[(size_t)BATCH * NKVH * HDIM * S_LEN];

// ================= mma.sync / ldmatrix / cp.async helpers =================
__device__ __forceinline__ void mma_f16(float* c, const uint32_t* a, const uint32_t* b)
{
    asm volatile(
        "mma.sync.aligned.m16n8k16.row.col.f32.f16.f16.f32 "
        "{%0,%1,%2,%3}, {%4,%5,%6,%7}, {%8,%9}, {%0,%1,%2,%3};"
        : "+f"(c[0]), "+f"(c[1]), "+f"(c[2]), "+f"(c[3])
        : "r"(a[0]), "r"(a[1]), "r"(a[2]), "r"(a[3]), "r"(b[0]), "r"(b[1]));
}
__device__ __forceinline__ void ldsm_x4(uint32_t* r, uint32_t addr)
{
    asm volatile("ldmatrix.sync.aligned.m8n8.x4.shared.b16 {%0,%1,%2,%3}, [%4];"
        : "=r"(r[0]), "=r"(r[1]), "=r"(r[2]), "=r"(r[3]) : "r"(addr));
}
__device__ __forceinline__ uint32_t smem_u32(const void* p) {
    uint32_t a;
    asm("{ .reg .u64 t; cvta.to.shared.u64 t, %1; cvt.u32.u64 %0, t; }" : "=r"(a) : "l"(p));
    return a;
}
__device__ __forceinline__ void cp_async16(uint32_t dst, const void* src) {
    asm volatile("cp.async.cg.shared.global [%0], [%1], 16;" :: "r"(dst), "l"(src));
}
#define CP_COMMIT() asm volatile("cp.async.commit_group;" ::: "memory")
#define CP_WAIT1()  asm volatile("cp.async.wait_group 1;" ::: "memory")
#define CP_WAIT0()  asm volatile("cp.async.wait_group 0;" ::: "memory")

__device__ __forceinline__ unsigned short f2h(float v) {
    __half h = __float2half_rn(v);
    return *(unsigned short*)&h;
}
__device__ __forceinline__ uint32_t pack2h(float a, float b) {
    __half2 h = __floats2half2_rn(a, b);
    return *(uint32_t*)&h;
}

// ================= conversion kernels =================
__global__ void convert_h(const float* __restrict__ src,
                          unsigned short* __restrict__ dst, int total)
{
    int i = blockIdx.x * blockDim.x + threadIdx.x;
    if (i >= total) return;
    dst[i] = f2h(src[i]);
}

// all 4 weight transposes in one launch. z: 0=wq(scaled) 1=wk 2=wv 3=wo
__global__ void transpose_all(const float* __restrict__ wq, const float* __restrict__ wk,
                              const float* __restrict__ wv, const float* __restrict__ wo,
                              unsigned short* __restrict__ wqh, unsigned short* __restrict__ wkh,
                              unsigned short* __restrict__ wvh, unsigned short* __restrict__ woh)
{
    const int z = blockIdx.z;
    const float* src; unsigned short* dst; int N; float scale = 1.0f;
    if (z == 0)      { src = wq; dst = wqh; N = 2048; scale = SCALE; }
    else if (z == 1) { src = wk; dst = wkh; N = 512; }
    else if (z == 2) { src = wv; dst = wvh; N = 512; }
    else             { src = wo; dst = woh; N = 2048; }
    if (blockIdx.x * 32 >= N) return;

    __shared__ float t[32][33];
    const int n0 = blockIdx.x * 32, k0 = blockIdx.y * 32;
    const int tx = threadIdx.x, ty = threadIdx.y;  // (32, 8)
    #pragma unroll
    for (int i = 0; i < 4; i++)
        t[ty + i * 8][tx] = src[(size_t)(k0 + ty + i * 8) * N + n0 + tx];
    __syncthreads();
    #pragma unroll
    for (int i = 0; i < 4; i++) {
        int n = ty + i * 8;
        dst[(size_t)(n0 + n) * HID + k0 + tx] = f2h(t[tx][n] * scale);
    }
}

// ================= rope table =================
__global__ void fill_rope_table()
{
    int idx = blockIdx.x * blockDim.x + threadIdx.x;
    if (idx >= S_LEN * 64) return;
    int d = idx & 63, pos = idx >> 6;
    double inv = pow(10000.0, -((double)(2 * d)) / 128.0);
    double cd, sd;
    sincos((double)pos * inv, &sd, &cd);
    g_rope_tab[idx] = make_float2((float)cd, (float)sd);
}

// ================= fp16 GEMM (R10 config): 256 thr, 128x128 tile, 2-stage =================
// modes: 0 = fp32 C; 1 = rope + fp16 row-major; 2 = fp16 transposed (vth)
#define KTILE    64
#define NT_STEPS (HID / KTILE)      // 32
#define APITCH   72                 // u16 smem pitch (144B)
#define TILE_U16 (128 * APITCH)     // 9216
#define BUF_U16  (2 * TILE_U16)     // A + B per stage
#define GEMM_SMEM (2 * BUF_U16 * 2) // 73728 B
#define PITCHF   132                // fp32 staging pitch (epilogue)

__device__ void gemm_mma_body(const unsigned short* __restrict__ Ah,
                              const unsigned short* __restrict__ Bh,
                              int row0, int col0,
                              int mode,
                              float* __restrict__ C, int ldc,            // mode 0
                              unsigned short* __restrict__ O16, int ldo, // mode 1
                              unsigned short* __restrict__ VT, int bg)   // mode 2
{
    extern __shared__ unsigned short sm[];
    const uint32_t sbase = smem_u32(sm);
    const int tid  = threadIdx.x;
    const int wid  = tid >> 5;
    const int lane = tid & 31;
    const int wm   = wid & 1;
    const int wn   = wid >> 1;
    const int g    = lane >> 2;
    const int tq   = lane & 3;

    const int lr   = lane & 7;
    const int oaR  = (lane & 8)  ? 8 : 0;
    const int oaC  = (lane & 16) ? 8 : 0;
    const int obR  = (lane & 16) ? 8 : 0;
    const int obC  = (lane & 8)  ? 8 : 0;
    const int rowA0 = wm * 64 + lr + oaR;
    const int rowB0 = wn * 32 + lr + obR;

    const int r    = tid >> 1;
    const int half = tid & 1;
    const unsigned short* pA = Ah + (size_t)(row0 + r) * HID + half * 32;
    const unsigned short* pB = Bh + (size_t)(col0 + r) * HID + half * 32;
    const uint32_t dsoff = 2u * (uint32_t)(r * APITCH + half * 32);

    float acc[4][4][4];
    #pragma unroll
    for (int mi = 0; mi < 4; mi++)
        #pragma unroll
        for (int ni = 0; ni < 4; ni++)
            #pragma unroll
            for (int e = 0; e < 4; e++) acc[mi][ni][e] = 0.0f;

    auto issue = [&](int t, int buf) {
        const int k0 = t * KTILE;
        const uint32_t a0 = sbase + 2u * (uint32_t)(buf * BUF_U16) + dsoff;
        const uint32_t b0 = a0 + 2u * TILE_U16;
        cp_async16(a0,      pA + k0);
        cp_async16(a0 + 16, pA + k0 + 8);
        cp_async16(a0 + 32, pA + k0 + 16);
        cp_async16(a0 + 48, pA + k0 + 24);
        cp_async16(b0,      pB + k0);
        cp_async16(b0 + 16, pB + k0 + 8);
        cp_async16(b0 + 32, pB + k0 + 16);
        cp_async16(b0 + 48, pB + k0 + 24);
    };

    issue(0, 0);
    CP_COMMIT();

    for (int t = 0; t < NT_STEPS; t++) {
        const int cur = t & 1;
        const bool has_next = (t + 1) < NT_STEPS;
        if (has_next) {
            issue(t + 1, cur ^ 1);
            CP_COMMIT();
            CP_WAIT1();
        } else {
            CP_WAIT0();
        }
        __syncthreads();

        const uint32_t aH = sbase + 2u * (uint32_t)(cur * BUF_U16);
        const uint32_t bH = aH + 2u * TILE_U16;

        #pragma unroll
        for (int ks = 0; ks < KTILE; ks += 16) {
            uint32_t bhf[2][4];
            #pragma unroll
            for (int jj = 0; jj < 2; jj++)
                ldsm_x4(bhf[jj], bH + 2u * (uint32_t)((rowB0 + jj * 16) * APITCH + ks + obC));
            #pragma unroll
            for (int mi = 0; mi < 4; mi++) {
                uint32_t ahf[4];
                ldsm_x4(ahf, aH + 2u * (uint32_t)((rowA0 + mi * 16) * APITCH + ks + oaC));
                #pragma unroll
                for (int jj = 0; jj < 2; jj++) {
                    mma_f16(acc[mi][2*jj],   ahf, &bhf[jj][0]);
                    mma_f16(acc[mi][2*jj+1], ahf, &bhf[jj][2]);
                }
            }
        }
        __syncthreads();
    }

    if (mode == 0) {
        #pragma unroll
        for (int mi = 0; mi < 4; mi++) {
            const int mrow = row0 + wm * 64 + mi * 16 + g;
            #pragma unroll
            for (int ni = 0; ni < 4; ni++) {
                const int ncol = col0 + wn * 32 + ni * 8 + tq * 2;
                *(float2*)(C + (size_t)mrow * ldc + ncol)       = make_float2(acc[mi][ni][0], acc[mi][ni][1]);
                *(float2*)(C + (size_t)(mrow + 8) * ldc + ncol) = make_float2(acc[mi][ni][2], acc[mi][ni][3]);
            }
        }
        return;
    }

    // ---- stage fp32 accumulators into smem ----
    float* stf = (float*)sm;
    #pragma unroll
    for (int mi = 0; mi < 4; mi++) {
        const int rl = wm * 64 + mi * 16 + g;
        #pragma unroll
        for (int ni = 0; ni < 4; ni++) {
            const int cl = wn * 32 + ni * 8 + tq * 2;
            stf[rl * PITCHF + cl]           = acc[mi][ni][0];
            stf[rl * PITCHF + cl + 1]       = acc[mi][ni][1];
            stf[(rl + 8) * PITCHF + cl]     = acc[mi][ni][2];
            stf[(rl + 8) * PITCHF + cl + 1] = acc[mi][ni][3];
        }
    }
    __syncthreads();

    if (mode == 1) {
        const int rr = tid >> 1;
        const int dbase = (tid & 1) * 32;
        const int pos = (row0 + rr) & (S_LEN - 1);
        unsigned short b1[32], b2[32];
        #pragma unroll
        for (int i = 0; i < 32; i++) {
            const int d = dbase + i;
            float x1 = stf[rr * PITCHF + d];
            float x2 = stf[rr * PITCHF + d + 64];
            float2 cs = g_rope_tab[pos * 64 + d];
            b1[i] = f2h(x1 * cs.x - x2 * cs.y);
            b2[i] = f2h(x2 * cs.x + x1 * cs.y);
        }
        unsigned short* o1 = O16 + (size_t)(row0 + rr) * ldo + col0 + dbase;
        #pragma unroll
        for (int j = 0; j < 4; j++) *(uint4*)(o1 + j * 8)      = ((uint4*)b1)[j];
        #pragma unroll
        for (int j = 0; j < 4; j++) *(uint4*)(o1 + 64 + j * 8) = ((uint4*)b2)[j];
    } else {
        const int d   = tid >> 1;
        const int kh2 = tid & 1;
        unsigned short vb[64];
        #pragma unroll
        for (int i = 0; i < 64; i++)
            vb[i] = f2h(stf[(kh2 * 64 + i) * PITCHF + d]);
        unsigned short* o = VT + ((size_t)bg * 128 + d) * S_LEN + (row0 & (S_LEN - 1)) + kh2 * 64;
        #pragma unroll
        for (int j = 0; j < 8; j++) *(uint4*)(o + j * 8) = ((uint4*)vb)[j];
    }
}

// fused QKV: grid.x 0..15 -> q heads, 16..19 -> k heads, 20..23 -> v heads
__global__ void __launch_bounds__(256, 2)
qkv_tc(const unsigned short* xh,
       const unsigned short* wqh, const unsigned short* wkh, const unsigned short* wvh,
       unsigned short* qh, unsigned short* kh, unsigned short* vth)
{
    const int bx = blockIdx.x;
    const int row0 = blockIdx.y * 128;
    if (bx < 16) {
        gemm_mma_body(xh, wqh, row0, bx * 128, 1, nullptr, 0, qh, 2048, nullptr, 0);
    } else if (bx < 20) {
        gemm_mma_body(xh, wkh, row0, (bx - 16) * 128, 1, nullptr, 0, kh, 512, nullptr, 0);
    } else {
        const int col0 = (bx - 20) * 128;
        const int bg = (row0 >> 11) * 4 + (col0 >> 7);
        gemm_mma_body(xh, wvh, row0, col0, 2, nullptr, 0, nullptr, 0, vth, bg);
    }
}

__global__ void __launch_bounds__(256, 2)
out_tc(const unsigned short* oh, const unsigned short* woh, float* C)
{
    gemm_mma_body(oh, woh, blockIdx.y * 128, blockIdx.x * 128, 0, C, 2048,
                  nullptr, 0, nullptr, 0);
}

// ================= flash attention: 256 thr, 128 q-rows per CTA, double-buffered K/V =================
// grid (S/128, NH, B); 8 warps; warp owns 16 q rows; kv tile 64 keys.
#define AKP 136
#define AVP 72
#define STG_U16 (64 * AKP + 128 * AVP)   // 17920 u16 per stage
#define SVOFF   (64 * AKP)
#define ATT_SMEM (2 * STG_U16 * 2)       // 71680 B

__global__ void __launch_bounds__(256)
attn_mma(const unsigned short* __restrict__ Qh,
         const unsigned short* __restrict__ Kh,
         const unsigned short* __restrict__ Vth,
         unsigned short* __restrict__ Oh)
{
    const int qt = blockIdx.x;      // 0..15 (128 q rows per block)
    const int h  = blockIdx.y;
    const int b  = blockIdx.z;
    const int g4 = h >> 2;
    const int bg = b * 4 + g4;

    extern __shared__ unsigned short smu[];
    const uint32_t sbase = smem_u32(smu);

    const int tid  = threadIdx.x;   // 0..255
    const int wid  = tid >> 5;      // 0..7
    const int lane = tid & 31;
    const int gr   = lane >> 2;
    const int tq   = lane & 3;

    const int lr    = lane & 7;
    const int off8a = (lane & 8)  ? 8 : 0;
    const int off8b = (lane & 16) ? 8 : 0;

    // ---- Q fragments: direct fp16 loads (pre-scaled, pre-roped) ----
    const int q0 = qt * 128 + wid * 16;
    const int grow0 = q0 + gr;          // global q row of acc rows [0..1]
    const int grow1 = q0 + gr + 8;      // global q row of acc rows [2..3]
    const unsigned short* pq0 = Qh + (size_t)(b * S_LEN + grow0) * 2048 + h * 128;
    const unsigned short* pq1 = Qh + (size_t)(b * S_LEN + grow1) * 2048 + h * 128;
    uint32_t qh[8][4];
    #pragma unroll
    for (int ks = 0; ks < 8; ks++) {
        qh[ks][0] = *(const uint32_t*)(pq0 + 16 * ks + 2 * tq);
        qh[ks][1] = *(const uint32_t*)(pq1 + 16 * ks + 2 * tq);
        qh[ks][2] = *(const uint32_t*)(pq0 + 16 * ks + 2 * tq + 8);
        qh[ks][3] = *(const uint32_t*)(pq1 + 16 * ks + 2 * tq + 8);
    }

    float o[16][4];
    #pragma unroll
    for (int j = 0; j < 16; j++)
        #pragma unroll
        for (int e = 0; e < 4; e++) o[j][e] = 0.0f;
    float m0 = -1e30f, m1 = -1e30f, l0 = 0.0f, l1 = 0.0f;

    const unsigned short* kh_base  = Kh  + ((size_t)(b * S_LEN) * 4 + g4) * 128;
    const unsigned short* vth_base = Vth + (size_t)bg * 128 * S_LEN;

    // cp.async tile loader (256 threads): K 64x128 (4 iters), V^T 128x64 (4 iters)
    auto load_tile = [&](int kt, int buf) {
        const uint32_t sb = sbase + 2u * (uint32_t)(buf * STG_U16);
        const unsigned short* src_k = kh_base + (size_t)(kt * 64) * 512;
        #pragma unroll
        for (int i = 0; i < 4; i++) {
            int idx = tid + i * 256;
            int row = idx >> 4, seg = (idx & 15) * 8;
            cp_async16(sb + 2u * (uint32_t)(row * AKP + seg), src_k + (size_t)row * 512 + seg);
        }
        const unsigned short* src_v = vth_base + kt * 64;
        #pragma unroll
        for (int i = 0; i < 4; i++) {
            int idx = tid + i * 256;
            int row = idx >> 3, seg = (idx & 7) * 8;
            cp_async16(sb + 2u * (uint32_t)(SVOFF + row * AVP + seg), src_v + (size_t)row * S_LEN + seg);
        }
    };

    const int nkt = 2 * qt + 2;     // kv tiles 0..2qt+1 cover cols <= qt*128+127

    load_tile(0, 0); CP_COMMIT();

    for (int kt = 0; kt < nkt; kt++) {
        const int buf = kt & 1;
        if (kt + 1 < nkt) {
            load_tile(kt + 1, buf ^ 1);
            CP_COMMIT();
            CP_WAIT1();
        } else {
            CP_WAIT0();
        }
        __syncthreads();

        const uint32_t stg = sbase + 2u * (uint32_t)(buf * STG_U16);

        // ---- scores ----
        float s[8][4];
        #pragma unroll
        for (int j = 0; j < 8; j++)
            #pragma unroll
            for (int e = 0; e < 4; e++) s[j][e] = 0.0f;

        #pragma unroll
        for (int jj = 0; jj < 4; jj++) {
            #pragma unroll
            for (int ks = 0; ks < 8; ks++) {
                uint32_t khf[4];
                ldsm_x4(khf, stg + 2u * (uint32_t)((16 * jj + off8b + lr) * AKP + 16 * ks + off8a));
                mma_f16(s[2*jj],   qh[ks], khf + 0);
                mma_f16(s[2*jj+1], qh[ks], khf + 2);
            }
        }

        // ---- causal mask (only last two tiles can cross the diagonal) ----
        if (kt >= 2 * qt) {
            const int colbase = kt * 64;
            #pragma unroll
            for (int j = 0; j < 8; j++) {
                int c0 = colbase + 8 * j + 2 * tq, c1 = c0 + 1;
                if (c0 > grow0) s[j][0] = -1e30f;
                if (c1 > grow0) s[j][1] = -1e30f;
                if (c0 > grow1) s[j][2] = -1e30f;
                if (c1 > grow1) s[j][3] = -1e30f;
            }
        }

        // ---- online softmax ----
        float mx0 = -1e30f, mx1 = -1e30f;
        #pragma unroll
        for (int j = 0; j < 8; j++) {
            mx0 = fmaxf(mx0, fmaxf(s[j][0], s[j][1]));
            mx1 = fmaxf(mx1, fmaxf(s[j][2], s[j][3]));
        }
        mx0 = fmaxf(mx0, __shfl_xor_sync(0xffffffffu, mx0, 1));
        mx0 = fmaxf(mx0, __shfl_xor_sync(0xffffffffu, mx0, 2));
        mx1 = fmaxf(mx1, __shfl_xor_sync(0xffffffffu, mx1, 1));
        mx1 = fmaxf(mx1, __shfl_xor_sync(0xffffffffu, mx1, 2));

        float mn0 = fmaxf(m0, mx0), mn1 = fmaxf(m1, mx1);
        float c0 = __expf(m0 - mn0), c1 = __expf(m1 - mn1);

        uint32_t ph[8][2];
        float sum0 = 0.0f, sum1 = 0.0f;
        #pragma unroll
        for (int j = 0; j < 8; j++) {
            float p0 = __expf(s[j][0] - mn0);
            float p1 = __expf(s[j][1] - mn0);
            float p2 = __expf(s[j][2] - mn1);
            float p3 = __expf(s[j][3] - mn1);
            sum0 += p0 + p1;
            sum1 += p2 + p3;
            ph[j][0] = pack2h(p0, p1);
            ph[j][1] = pack2h(p2, p3);
        }
        sum0 += __shfl_xor_sync(0xffffffffu, sum0, 1);
        sum0 += __shfl_xor_sync(0xffffffffu, sum0, 2);
        sum1 += __shfl_xor_sync(0xffffffffu, sum1, 1);
        sum1 += __shfl_xor_sync(0xffffffffu, sum1, 2);
        l0 = l0 * c0 + sum0;
        l1 = l1 * c1 + sum1;
        m0 = mn0; m1 = mn1;
        #pragma unroll
        for (int j = 0; j < 16; j++) {
            o[j][0] *= c0; o[j][1] *= c0;
            o[j][2] *= c1; o[j][3] *= c1;
        }

        // ---- PV ----
        #pragma unroll
        for (int ks = 0; ks < 4; ks++) {
            uint32_t ah4[4] = { ph[2*ks][0], ph[2*ks][1], ph[2*ks+1][0], ph[2*ks+1][1] };
            #pragma unroll
            for (int jj = 0; jj < 8; jj++) {
                uint32_t vhf[4];
                ldsm_x4(vhf, stg + 2u * (uint32_t)(SVOFF + (16 * jj + off8b + lr) * AVP + 16 * ks + off8a));
                mma_f16(o[2*jj],   ah4, vhf + 0);
                mma_f16(o[2*jj+1], ah4, vhf + 2);
            }
        }
        __syncthreads();
    }

    // ---- epilogue: normalize, store fp16 ----
    const float inv0 = 1.0f / l0, inv1 = 1.0f / l1;
    const size_t rowA = (size_t)(b * S_LEN + grow0) * 2048 + h * 128;
    const size_t rowB = (size_t)(b * S_LEN + grow1) * 2048 + h * 128;
    #pragma unroll
    for (int j = 0; j < 16; j++) {
        const int col = 8 * j + 2 * tq;
        *(uint32_t*)(Oh + rowA + col) = pack2h(o[j][0] * inv0, o[j][1] * inv0);
        *(uint32_t*)(Oh + rowB + col) = pack2h(o[j][2] * inv1, o[j][3] * inv1);
    }
}

// ================= launch =================
extern "C" void kernel_launch(void* const* d_in, const int* in_sizes, int n_in,
                              void* d_out, int out_size)
{
    const float* x  = (const float*)d_in[0];
    const float* wq = (const float*)d_in[1];
    const float* wk = (const float*)d_in[2];
    const float* wv = (const float*)d_in[3];
    const float* wo = (const float*)d_in[4];
    float* out = (float*)d_out;

    unsigned short *xh, *oh, *wqh, *wkh, *wvh, *woh, *qh, *kh, *vth;
    cudaGetSymbolAddress((void**)&xh, g_xh);
    cudaGetSymbolAddress((void**)&oh, g_oh);
    cudaGetSymbolAddress((void**)&wqh, g_wqh);
    cudaGetSymbolAddress((void**)&wkh, g_wkh);
    cudaGetSymbolAddress((void**)&wvh, g_wvh);
    cudaGetSymbolAddress((void**)&woh, g_woh);
    cudaGetSymbolAddress((void**)&qh, g_qh);
    cudaGetSymbolAddress((void**)&kh, g_kh);
    cudaGetSymbolAddress((void**)&vth, g_vth);

    cudaFuncSetAttribute(qkv_tc, cudaFuncAttributeMaxDynamicSharedMemorySize, GEMM_SMEM);
    cudaFuncSetAttribute(out_tc, cudaFuncAttributeMaxDynamicSharedMemorySize, GEMM_SMEM);
    cudaFuncSetAttribute(attn_mma, cudaFuncAttributeMaxDynamicSharedMemorySize, ATT_SMEM);

    // 0. rope table + operand conversion
    fill_rope_table<<<(S_LEN * 64 + 255) / 256, 256>>>();
    convert_h<<<(ROWS * HID + 255) / 256, 256>>>(x, xh, ROWS * HID);
    transpose_all<<<dim3(64, 64, 4), dim3(32, 8)>>>(wq, wk, wv, wo, wqh, wkh, wvh, woh);

    // 1. fused QKV projections + rope + quantize + V-transpose (R10 GEMM config)
    qkv_tc<<<dim3(24, ROWS / 128), 256, GEMM_SMEM>>>(xh, wqh, wkh, wvh, qh, kh, vth);

    // 2. flash attention (fp16 mma, 128 q-rows/CTA, double-buffered); writes oh directly
    attn_mma<<<dim3(S_LEN / 128, NHEAD, BATCH), 256, ATT_SMEM>>>(qh, kh, vth, oh);

    // 3. output projection
    out_tc<<<dim3(HID / 128, ROWS / 128), 256, GEMM_SMEM>>>(oh, woh, out);
}

// round 16
// speedup vs baseline: 1.2177x; 1.0666x over previous
#include <cuda_runtime.h>
#include <cuda_fp16.h>
#include <cstdint>
#include <cstddef>

// ---------------- problem constants ----------------
#define S_LEN  2048
#define HID    2048
#define NHEAD  16
#define NKVH   4
#define HDIM   128
#define BATCH  2
#define ROWS   (BATCH * S_LEN)      // 4096
#define SCALE  0.08838834764831845f // 1/sqrt(128)

// ---------------- scratch (static device memory; no allocations) ----------------
__device__ float2 g_rope_tab[(size_t)S_LEN * 64];

// fp16 operands
__device__ unsigned short g_xh[(size_t)ROWS * HID];
__device__ unsigned short g_oh[(size_t)ROWS * HID];
__device__ unsigned short g_wqh[(size_t)2048 * HID];   // pre-scaled by SCALE
__device__ unsigned short g_wkh[(size_t)512 * HID];
__device__ unsigned short g_wvh[(size_t)512 * HID];
__device__ unsigned short g_woh[(size_t)2048 * HID];
__device__ unsigned short g_qh[(size_t)ROWS * NHEAD * HDIM];   // roped, scaled
__device__ unsigned short g_kh[(size_t)ROWS * NKVH * HDIM];    // roped
__device__ unsigned short g_vth[(size_t)BATCH * NKVH * HDIM * S_LEN];

// ================= mma.sync / ldmatrix / cp.async helpers =================
__device__ __forceinline__ void mma_f16(float* c, const uint32_t* a, const uint32_t* b)
{
    asm volatile(
        "mma.sync.aligned.m16n8k16.row.col.f32.f16.f16.f32 "
        "{%0,%1,%2,%3}, {%4,%5,%6,%7}, {%8,%9}, {%0,%1,%2,%3};"
        : "+f"(c[0]), "+f"(c[1]), "+f"(c[2]), "+f"(c[3])
        : "r"(a[0]), "r"(a[1]), "r"(a[2]), "r"(a[3]), "r"(b[0]), "r"(b[1]));
}
__device__ __forceinline__ void ldsm_x4(uint32_t* r, uint32_t addr)
{
    asm volatile("ldmatrix.sync.aligned.m8n8.x4.shared.b16 {%0,%1,%2,%3}, [%4];"
        : "=r"(r[0]), "=r"(r[1]), "=r"(r[2]), "=r"(r[3]) : "r"(addr));
}
__device__ __forceinline__ uint32_t smem_u32(const void* p) {
    uint32_t a;
    asm("{ .reg .u64 t; cvta.to.shared.u64 t, %1; cvt.u32.u64 %0, t; }" : "=r"(a) : "l"(p));
    return a;
}
__device__ __forceinline__ void cp_async16(uint32_t dst, const void* src) {
    asm volatile("cp.async.cg.shared.global [%0], [%1], 16;" :: "r"(dst), "l"(src));
}
#define CP_COMMIT() asm volatile("cp.async.commit_group;" ::: "memory")
#define CP_WAIT0()  asm volatile("cp.async.wait_group 0;" ::: "memory")

__device__ __forceinline__ unsigned short f2h(float v) {
    __half h = __float2half_rn(v);
    return *(unsigned short*)&h;
}
__device__ __forceinline__ uint32_t pack2h(float a, float b) {
    __half2 h = __floats2half2_rn(a, b);
    return *(uint32_t*)&h;
}

// ================= conversion kernels =================
__global__ void convert_h(const float* __restrict__ src,
                          unsigned short* __restrict__ dst, int total)
{
    int i = blockIdx.x * blockDim.x + threadIdx.x;
    if (i >= total) return;
    dst[i] = f2h(src[i]);
}

// all 4 weight transposes in one launch. z: 0=wq(scaled) 1=wk 2=wv 3=wo
__global__ void transpose_all(const float* __restrict__ wq, const float* __restrict__ wk,
                              const float* __restrict__ wv, const float* __restrict__ wo,
                              unsigned short* __restrict__ wqh, unsigned short* __restrict__ wkh,
                              unsigned short* __restrict__ wvh, unsigned short* __restrict__ woh)
{
    const int z = blockIdx.z;
    const float* src; unsigned short* dst; int N; float scale = 1.0f;
    if (z == 0)      { src = wq; dst = wqh; N = 2048; scale = SCALE; }
    else if (z == 1) { src = wk; dst = wkh; N = 512; }
    else if (z == 2) { src = wv; dst = wvh; N = 512; }
    else             { src = wo; dst = woh; N = 2048; }
    if (blockIdx.x * 32 >= N) return;

    __shared__ float t[32][33];
    const int n0 = blockIdx.x * 32, k0 = blockIdx.y * 32;
    const int tx = threadIdx.x, ty = threadIdx.y;  // (32, 8)
    #pragma unroll
    for (int i = 0; i < 4; i++)
        t[ty + i * 8][tx] = src[(size_t)(k0 + ty + i * 8) * N + n0 + tx];
    __syncthreads();
    #pragma unroll
    for (int i = 0; i < 4; i++) {
        int n = ty + i * 8;
        dst[(size_t)(n0 + n) * HID + k0 + tx] = f2h(t[tx][n] * scale);
    }
}

// ================= rope table =================
__global__ void fill_rope_table()
{
    int idx = blockIdx.x * blockDim.x + threadIdx.x;
    if (idx >= S_LEN * 64) return;
    int d = idx & 63, pos = idx >> 6;
    double inv = pow(10000.0, -((double)(2 * d)) / 128.0);
    double cd, sd;
    sincos((double)pos * inv, &sd, &cd);
    g_rope_tab[idx] = make_float2((float)cd, (float)sd);
}

// ================= fp16 GEMM: 256 thr, 128x128 tile, 2-stage, single-sync =================
// modes: 0 = fp32 C; 1 = rope + fp16 row-major; 2 = fp16 transposed (vth)
#define KTILE    64
#define NT_STEPS (HID / KTILE)      // 32
#define APITCH   72                 // u16 smem pitch (144B)
#define TILE_U16 (128 * APITCH)     // 9216
#define BUF_U16  (2 * TILE_U16)     // A + B per stage
#define GEMM_SMEM (2 * BUF_U16 * 2) // 73728 B
#define PITCHF   132                // fp32 staging pitch (epilogue)

__device__ void gemm_mma_body(const unsigned short* __restrict__ Ah,
                              const unsigned short* __restrict__ Bh,
                              int row0, int col0,
                              int mode,
                              float* __restrict__ C, int ldc,            // mode 0
                              unsigned short* __restrict__ O16, int ldo, // mode 1
                              unsigned short* __restrict__ VT, int bg)   // mode 2
{
    extern __shared__ unsigned short sm[];
    const uint32_t sbase = smem_u32(sm);
    const int tid  = threadIdx.x;
    const int wid  = tid >> 5;
    const int lane = tid & 31;
    const int wm   = wid & 1;
    const int wn   = wid >> 1;
    const int g    = lane >> 2;
    const int tq   = lane & 3;

    const int lr   = lane & 7;
    const int oaR  = (lane & 8)  ? 8 : 0;
    const int oaC  = (lane & 16) ? 8 : 0;
    const int obR  = (lane & 16) ? 8 : 0;
    const int obC  = (lane & 8)  ? 8 : 0;
    const int rowA0 = wm * 64 + lr + oaR;
    const int rowB0 = wn * 32 + lr + obR;

    const int r    = tid >> 1;
    const int half = tid & 1;
    const unsigned short* pA = Ah + (size_t)(row0 + r) * HID + half * 32;
    const unsigned short* pB = Bh + (size_t)(col0 + r) * HID + half * 32;
    const uint32_t dsoff = 2u * (uint32_t)(r * APITCH + half * 32);

    float acc[4][4][4];
    #pragma unroll
    for (int mi = 0; mi < 4; mi++)
        #pragma unroll
        for (int ni = 0; ni < 4; ni++)
            #pragma unroll
            for (int e = 0; e < 4; e++) acc[mi][ni][e] = 0.0f;

    auto issue = [&](int t, int buf) {
        const int k0 = t * KTILE;
        const uint32_t a0 = sbase + 2u * (uint32_t)(buf * BUF_U16) + dsoff;
        const uint32_t b0 = a0 + 2u * TILE_U16;
        cp_async16(a0,      pA + k0);
        cp_async16(a0 + 16, pA + k0 + 8);
        cp_async16(a0 + 32, pA + k0 + 16);
        cp_async16(a0 + 48, pA + k0 + 24);
        cp_async16(b0,      pB + k0);
        cp_async16(b0 + 16, pB + k0 + 8);
        cp_async16(b0 + 32, pB + k0 + 16);
        cp_async16(b0 + 48, pB + k0 + 24);
    };

    issue(0, 0);
    CP_COMMIT();

    for (int t = 0; t < NT_STEPS; t++) {
        const int cur = t & 1;
        CP_WAIT0();              // tile t complete (only pending group)
        __syncthreads();         // all warps done with tile t-1, tile t visible
        if (t + 1 < NT_STEPS) {
            issue(t + 1, cur ^ 1);   // safe: everyone is past tile t-1 (buffer cur^1)
            CP_COMMIT();
        }

        const uint32_t aH = sbase + 2u * (uint32_t)(cur * BUF_U16);
        const uint32_t bH = aH + 2u * TILE_U16;

        #pragma unroll
        for (int ks = 0; ks < KTILE; ks += 16) {
            uint32_t bhf[2][4];
            #pragma unroll
            for (int jj = 0; jj < 2; jj++)
                ldsm_x4(bhf[jj], bH + 2u * (uint32_t)((rowB0 + jj * 16) * APITCH + ks + obC));
            #pragma unroll
            for (int mi = 0; mi < 4; mi++) {
                uint32_t ahf[4];
                ldsm_x4(ahf, aH + 2u * (uint32_t)((rowA0 + mi * 16) * APITCH + ks + oaC));
                #pragma unroll
                for (int jj = 0; jj < 2; jj++) {
                    mma_f16(acc[mi][2*jj],   ahf, &bhf[jj][0]);
                    mma_f16(acc[mi][2*jj+1], ahf, &bhf[jj][2]);
                }
            }
        }
    }

    if (mode == 0) {
        #pragma unroll
        for (int mi = 0; mi < 4; mi++) {
            const int mrow = row0 + wm * 64 + mi * 16 + g;
            #pragma unroll
            for (int ni = 0; ni < 4; ni++) {
                const int ncol = col0 + wn * 32 + ni * 8 + tq * 2;
                *(float2*)(C + (size_t)mrow * ldc + ncol)       = make_float2(acc[mi][ni][0], acc[mi][ni][1]);
                *(float2*)(C + (size_t)(mrow + 8) * ldc + ncol) = make_float2(acc[mi][ni][2], acc[mi][ni][3]);
            }
        }
        return;
    }

    __syncthreads();   // all warps done reading operand smem before staging overwrite

    // ---- stage fp32 accumulators into smem ----
    float* stf = (float*)sm;
    #pragma unroll
    for (int mi = 0; mi < 4; mi++) {
        const int rl = wm * 64 + mi * 16 + g;
        #pragma unroll
        for (int ni = 0; ni < 4; ni++) {
            const int cl = wn * 32 + ni * 8 + tq * 2;
            stf[rl * PITCHF + cl]           = acc[mi][ni][0];
            stf[rl * PITCHF + cl + 1]       = acc[mi][ni][1];
            stf[(rl + 8) * PITCHF + cl]     = acc[mi][ni][2];
            stf[(rl + 8) * PITCHF + cl + 1] = acc[mi][ni][3];
        }
    }
    __syncthreads();

    if (mode == 1) {
        const int rr = tid >> 1;
        const int dbase = (tid & 1) * 32;
        const int pos = (row0 + rr) & (S_LEN - 1);
        unsigned short b1[32], b2[32];
        #pragma unroll
        for (int i = 0; i < 32; i++) {
            const int d = dbase + i;
            float x1 = stf[rr * PITCHF + d];
            float x2 = stf[rr * PITCHF + d + 64];
            float2 cs = g_rope_tab[pos * 64 + d];
            b1[i] = f2h(x1 * cs.x - x2 * cs.y);
            b2[i] = f2h(x2 * cs.x + x1 * cs.y);
        }
        unsigned short* o1 = O16 + (size_t)(row0 + rr) * ldo + col0 + dbase;
        #pragma unroll
        for (int j = 0; j < 4; j++) *(uint4*)(o1 + j * 8)      = ((uint4*)b1)[j];
        #pragma unroll
        for (int j = 0; j < 4; j++) *(uint4*)(o1 + 64 + j * 8) = ((uint4*)b2)[j];
    } else {
        const int d   = tid >> 1;
        const int kh2 = tid & 1;
        unsigned short vb[64];
        #pragma unroll
        for (int i = 0; i < 64; i++)
            vb[i] = f2h(stf[(kh2 * 64 + i) * PITCHF + d]);
        unsigned short* o = VT + ((size_t)bg * 128 + d) * S_LEN + (row0 & (S_LEN - 1)) + kh2 * 64;
        #pragma unroll
        for (int j = 0; j < 8; j++) *(uint4*)(o + j * 8) = ((uint4*)vb)[j];
    }
}

// fused QKV: grid.x 0..15 -> q heads, 16..19 -> k heads, 20..23 -> v heads
__global__ void __launch_bounds__(256, 2)
qkv_tc(const unsigned short* xh,
       const unsigned short* wqh, const unsigned short* wkh, const unsigned short* wvh,
       unsigned short* qh, unsigned short* kh, unsigned short* vth)
{
    const int bx = blockIdx.x;
    const int row0 = blockIdx.y * 128;
    if (bx < 16) {
        gemm_mma_body(xh, wqh, row0, bx * 128, 1, nullptr, 0, qh, 2048, nullptr, 0);
    } else if (bx < 20) {
        gemm_mma_body(xh, wkh, row0, (bx - 16) * 128, 1, nullptr, 0, kh, 512, nullptr, 0);
    } else {
        const int col0 = (bx - 20) * 128;
        const int bg = (row0 >> 11) * 4 + (col0 >> 7);
        gemm_mma_body(xh, wvh, row0, col0, 2, nullptr, 0, nullptr, 0, vth, bg);
    }
}

__global__ void __launch_bounds__(256, 2)
out_tc(const unsigned short* oh, const unsigned short* woh, float* C)
{
    gemm_mma_body(oh, woh, blockIdx.y * 128, blockIdx.x * 128, 0, C, 2048,
                  nullptr, 0, nullptr, 0);
}

// ================= flash attention: diagonal-paired q-blocks, single-sync =================
// grid (S/256, NH, B): CTA processes q-blocks {qx, 15-qx} -> uniform 34 tile-units.
// 256 thr, 8 warps, warp owns 16 q rows of the 128-row block; kv tile 64 keys.
#define AKP 136
#define AVP 72
#define STG_U16 (64 * AKP + 128 * AVP)   // 17920 u16 per stage
#define SVOFF   (64 * AKP)
#define ATT_SMEM (2 * STG_U16 * 2)       // 71680 B
#define NQB (S_LEN / 128)                // 16 q-blocks

__global__ void __launch_bounds__(256)
attn_mma(const unsigned short* __restrict__ Qh,
         const unsigned short* __restrict__ Kh,
         const unsigned short* __restrict__ Vth,
         unsigned short* __restrict__ Oh)
{
    const int qx = blockIdx.x;      // 0..7
    const int h  = blockIdx.y;
    const int b  = blockIdx.z;
    const int g4 = h >> 2;
    const int bg = b * 4 + g4;

    extern __shared__ unsigned short smu[];
    const uint32_t sbase = smem_u32(smu);

    const int tid  = threadIdx.x;   // 0..255
    const int wid  = tid >> 5;      // 0..7
    const int lane = tid & 31;
    const int gr   = lane >> 2;
    const int tq   = lane & 3;

    const int lr    = lane & 7;
    const int off8a = (lane & 8)  ? 8 : 0;
    const int off8b = (lane & 16) ? 8 : 0;

    const unsigned short* kh_base  = Kh  + ((size_t)(b * S_LEN) * 4 + g4) * 128;
    const unsigned short* vth_base = Vth + (size_t)bg * 128 * S_LEN;

    auto load_tile = [&](int kt, int buf) {
        const uint32_t sb = sbase + 2u * (uint32_t)(buf * STG_U16);
        const unsigned short* src_k = kh_base + (size_t)(kt * 64) * 512;
        #pragma unroll
        for (int i = 0; i < 4; i++) {
            int idx = tid + i * 256;
            int row = idx >> 4, seg = (idx & 15) * 8;
            cp_async16(sb + 2u * (uint32_t)(row * AKP + seg), src_k + (size_t)row * 512 + seg);
        }
        const unsigned short* src_v = vth_base + kt * 64;
        #pragma unroll
        for (int i = 0; i < 4; i++) {
            int idx = tid + i * 256;
            int row = idx >> 3, seg = (idx & 7) * 8;
            cp_async16(sb + 2u * (uint32_t)(SVOFF + row * AVP + seg), src_v + (size_t)row * S_LEN + seg);
        }
    };

    #pragma unroll 1
    for (int pass = 0; pass < 2; pass++) {
        const int qb = pass ? (NQB - 1 - qx) : qx;

        // ---- Q fragments: direct fp16 loads (pre-scaled, pre-roped) ----
        const int q0 = qb * 128 + wid * 16;
        const int grow0 = q0 + gr;
        const int grow1 = q0 + gr + 8;
        const unsigned short* pq0 = Qh + (size_t)(b * S_LEN + grow0) * 2048 + h * 128;
        const unsigned short* pq1 = Qh + (size_t)(b * S_LEN + grow1) * 2048 + h * 128;
        uint32_t qhf[8][4];
        #pragma unroll
        for (int ks = 0; ks < 8; ks++) {
            qhf[ks][0] = *(const uint32_t*)(pq0 + 16 * ks + 2 * tq);
            qhf[ks][1] = *(const uint32_t*)(pq1 + 16 * ks + 2 * tq);
            qhf[ks][2] = *(const uint32_t*)(pq0 + 16 * ks + 2 * tq + 8);
            qhf[ks][3] = *(const uint32_t*)(pq1 + 16 * ks + 2 * tq + 8);
        }

        float o[16][4];
        #pragma unroll
        for (int j = 0; j < 16; j++)
            #pragma unroll
            for (int e = 0; e < 4; e++) o[j][e] = 0.0f;
        float m0 = -1e30f, m1 = -1e30f, l0 = 0.0f, l1 = 0.0f;

        const int nkt = 2 * qb + 2;

        __syncthreads();   // protect smem buffers from previous pass's readers
        load_tile(0, 0);
        CP_COMMIT();

        for (int kt = 0; kt < nkt; kt++) {
            const int buf = kt & 1;
            CP_WAIT0();            // tile kt ready (only pending group)
            __syncthreads();       // all warps past tile kt-1; tile kt visible
            if (kt + 1 < nkt) {
                load_tile(kt + 1, buf ^ 1);
                CP_COMMIT();
            }

            const uint32_t stg = sbase + 2u * (uint32_t)(buf * STG_U16);

            // ---- scores ----
            float s[8][4];
            #pragma unroll
            for (int j = 0; j < 8; j++)
                #pragma unroll
                for (int e = 0; e < 4; e++) s[j][e] = 0.0f;

            #pragma unroll
            for (int jj = 0; jj < 4; jj++) {
                #pragma unroll
                for (int ks = 0; ks < 8; ks++) {
                    uint32_t khf[4];
                    ldsm_x4(khf, stg + 2u * (uint32_t)((16 * jj + off8b + lr) * AKP + 16 * ks + off8a));
                    mma_f16(s[2*jj],   qhf[ks], khf + 0);
                    mma_f16(s[2*jj+1], qhf[ks], khf + 2);
                }
            }

            // ---- causal mask (only last two tiles cross the diagonal) ----
            if (kt >= 2 * qb) {
                const int colbase = kt * 64;
                #pragma unroll
                for (int j = 0; j < 8; j++) {
                    int c0 = colbase + 8 * j + 2 * tq, c1 = c0 + 1;
                    if (c0 > grow0) s[j][0] = -1e30f;
                    if (c1 > grow0) s[j][1] = -1e30f;
                    if (c0 > grow1) s[j][2] = -1e30f;
                    if (c1 > grow1) s[j][3] = -1e30f;
                }
            }

            // ---- online softmax ----
            float mx0 = -1e30f, mx1 = -1e30f;
            #pragma unroll
            for (int j = 0; j < 8; j++) {
                mx0 = fmaxf(mx0, fmaxf(s[j][0], s[j][1]));
                mx1 = fmaxf(mx1, fmaxf(s[j][2], s[j][3]));
            }
            mx0 = fmaxf(mx0, __shfl_xor_sync(0xffffffffu, mx0, 1));
            mx0 = fmaxf(mx0, __shfl_xor_sync(0xffffffffu, mx0, 2));
            mx1 = fmaxf(mx1, __shfl_xor_sync(0xffffffffu, mx1, 1));
            mx1 = fmaxf(mx1, __shfl_xor_sync(0xffffffffu, mx1, 2));

            float mn0 = fmaxf(m0, mx0), mn1 = fmaxf(m1, mx1);
            float c0 = __expf(m0 - mn0), c1 = __expf(m1 - mn1);

            uint32_t ph[8][2];
            float sum0 = 0.0f, sum1 = 0.0f;
            #pragma unroll
            for (int j = 0; j < 8; j++) {
                float p0 = __expf(s[j][0] - mn0);
                float p1 = __expf(s[j][1] - mn0);
                float p2 = __expf(s[j][2] - mn1);
                float p3 = __expf(s[j][3] - mn1);
                sum0 += p0 + p1;
                sum1 += p2 + p3;
                ph[j][0] = pack2h(p0, p1);
                ph[j][1] = pack2h(p2, p3);
            }
            sum0 += __shfl_xor_sync(0xffffffffu, sum0, 1);
            sum0 += __shfl_xor_sync(0xffffffffu, sum0, 2);
            sum1 += __shfl_xor_sync(0xffffffffu, sum1, 1);
            sum1 += __shfl_xor_sync(0xffffffffu, sum1, 2);
            l0 = l0 * c0 + sum0;
            l1 = l1 * c1 + sum1;
            m0 = mn0; m1 = mn1;
            #pragma unroll
            for (int j = 0; j < 16; j++) {
                o[j][0] *= c0; o[j][1] *= c0;
                o[j][2] *= c1; o[j][3] *= c1;
            }

            // ---- PV ----
            #pragma unroll
            for (int ks = 0; ks < 4; ks++) {
                uint32_t ah4[4] = { ph[2*ks][0], ph[2*ks][1], ph[2*ks+1][0], ph[2*ks+1][1] };
                #pragma unroll
                for (int jj = 0; jj < 8; jj++) {
                    uint32_t vhf[4];
                    ldsm_x4(vhf, stg + 2u * (uint32_t)(SVOFF + (16 * jj + off8b + lr) * AVP + 16 * ks + off8a));
                    mma_f16(o[2*jj],   ah4, vhf + 0);
                    mma_f16(o[2*jj+1], ah4, vhf + 2);
                }
            }
        }

        // ---- epilogue: normalize, store fp16 ----
        const float inv0 = 1.0f / l0, inv1 = 1.0f / l1;
        const size_t rowA = (size_t)(b * S_LEN + grow0) * 2048 + h * 128;
        const size_t rowB = (size_t)(b * S_LEN + grow1) * 2048 + h * 128;
        #pragma unroll
        for (int j = 0; j < 16; j++) {
            const int col = 8 * j + 2 * tq;
            *(uint32_t*)(Oh + rowA + col) = pack2h(o[j][0] * inv0, o[j][1] * inv0);
            *(uint32_t*)(Oh + rowB + col) = pack2h(o[j][2] * inv1, o[j][3] * inv1);
        }
    }
}

// ================= launch =================
extern "C" void kernel_launch(void* const* d_in, const int* in_sizes, int n_in,
                              void* d_out, int out_size)
{
    const float* x  = (const float*)d_in[0];
    const float* wq = (const float*)d_in[1];
    const float* wk = (const float*)d_in[2];
    const float* wv = (const float*)d_in[3];
    const float* wo = (const float*)d_in[4];
    float* out = (float*)d_out;

    unsigned short *xh, *oh, *wqh, *wkh, *wvh, *woh, *qh, *kh, *vth;
    cudaGetSymbolAddress((void**)&xh, g_xh);
    cudaGetSymbolAddress((void**)&oh, g_oh);
    cudaGetSymbolAddress((void**)&wqh, g_wqh);
    cudaGetSymbolAddress((void**)&wkh, g_wkh);
    cudaGetSymbolAddress((void**)&wvh, g_wvh);
    cudaGetSymbolAddress((void**)&woh, g_woh);
    cudaGetSymbolAddress((void**)&qh, g_qh);
    cudaGetSymbolAddress((void**)&kh, g_kh);
    cudaGetSymbolAddress((void**)&vth, g_vth);

    cudaFuncSetAttribute(qkv_tc, cudaFuncAttributeMaxDynamicSharedMemorySize, GEMM_SMEM);
    cudaFuncSetAttribute(out_tc, cudaFuncAttributeMaxDynamicSharedMemorySize, GEMM_SMEM);
    cudaFuncSetAttribute(attn_mma, cudaFuncAttributeMaxDynamicSharedMemorySize, ATT_SMEM);

    // 0. rope table + operand conversion
    fill_rope_table<<<(S_LEN * 64 + 255) / 256, 256>>>();
    convert_h<<<(ROWS * HID + 255) / 256, 256>>>(x, xh, ROWS * HID);
    transpose_all<<<dim3(64, 64, 4), dim3(32, 8)>>>(wq, wk, wv, wo, wqh, wkh, wvh, woh);

    // 1. fused QKV projections + rope + quantize + V-transpose
    qkv_tc<<<dim3(24, ROWS / 128), 256, GEMM_SMEM>>>(xh, wqh, wkh, wvh, qh, kh, vth);

    // 2. flash attention (diagonal-paired q-blocks, uniform load)
    attn_mma<<<dim3(S_LEN / 256, NHEAD, BATCH), 256, ATT_SMEM>>>(qh, kh, vth, oh);

    // 3. output projection
    out_tc<<<dim3(HID / 128, ROWS / 128), 256, GEMM_SMEM>>>(oh, woh, out);
}